// round 6
// baseline (speedup 1.0000x reference)
#include <cuda_runtime.h>
#include <cuda_bf16.h>
#include <math.h>
#include <stdint.h>

// Problem constants
#define Bb 4
#define Tt 2048
#define Dd 2048
#define Hh 16
#define Gg 4
#define Kk 128
#define Rr 4          // H / G
#define EPS 1e-6f
#define ROPE_BASE 10000.0f
#define SOFTMAX_SCALE 0.08838834764831845f  // K^-0.5

#define MTOT (Bb * Tt)          // 8192 rows

// --------------------------- scratch (device globals; no mallocs) ------------
__device__ float g_q[(size_t)MTOT * Hh * Kk];     // 64 MB
__device__ float g_k[(size_t)MTOT * Gg * Kk];     // 16 MB
__device__ float g_v[(size_t)MTOT * Gg * Kk];     // 16 MB
__device__ float g_attn[(size_t)MTOT * Hh * Kk];  // 64 MB
__device__ int   g_pos[MTOT];

// =============================================================================
// TF32 tensor-core GEMM:  C[M,N] = A[M,Kd] @ B[Kd,N]   (all row-major fp32)
// CTA tile 128x128, BK=32, 256 threads (8 warps, 2x4 warp grid, warp tile 64x32)
// mma.sync.aligned.m16n8k8.row.col.f32.tf32.tf32.f32, cp.async double buffering.
// Requires M%128==0, N%128==0, Kd%32==0.
// =============================================================================
#define A_STRIDE 36            // 128 rows x 36  (pad 4) -> conflict-free A frags
#define B_STRIDE 136           // 32 rows x 136  (pad 8) -> conflict-free B frags
#define A_SZ (128 * A_STRIDE)  // floats per buffer
#define B_SZ (32 * B_STRIDE)
#define GEMM_SMEM_BYTES ((2 * A_SZ + 2 * B_SZ) * 4)   // 71680 B

__device__ __forceinline__ uint32_t f2tf32(float x) {
    uint32_t u;
    asm("cvt.rna.tf32.f32 %0, %1;" : "=r"(u) : "f"(x));
    return u;
}

__global__ __launch_bounds__(256)
void gemm_tf32_kernel(int M, int N, int Kd,
                      const float* __restrict__ A,
                      const float* __restrict__ B,
                      float* __restrict__ C) {
    extern __shared__ float sm[];
    float* As = sm;               // [2][128][A_STRIDE]
    float* Bsm = sm + 2 * A_SZ;   // [2][32][B_STRIDE]

    const int tid  = threadIdx.x;
    const int lane = tid & 31;
    const int wid  = tid >> 5;
    const int warpM = wid & 1;    // 0..1 (64 rows each)
    const int warpN = wid >> 1;   // 0..3 (32 cols each)

    const float* Ag = A + (size_t)blockIdx.y * 128 * Kd;
    const float* Bg = B + (size_t)blockIdx.x * 128;

    const uint32_t as_base = (uint32_t)__cvta_generic_to_shared(As);
    const uint32_t bs_base = (uint32_t)__cvta_generic_to_shared(Bsm);

    float acc[4][4][4];
#pragma unroll
    for (int i = 0; i < 4; i++)
#pragma unroll
        for (int j = 0; j < 4; j++)
#pragma unroll
            for (int r = 0; r < 4; r++) acc[i][j][r] = 0.f;

    auto issue_loads = [&](int buf, int k0) {
        // A tile: 128 x 32 floats, 1024 float4, 4 per thread
#pragma unroll
        for (int i = 0; i < 4; i++) {
            int idx = tid + i * 256;
            int r = idx >> 3, c = (idx & 7) * 4;
            uint32_t dst = as_base + (uint32_t)(buf * A_SZ + r * A_STRIDE + c) * 4u;
            const float* src = Ag + (size_t)r * Kd + k0 + c;
            asm volatile("cp.async.cg.shared.global [%0], [%1], 16;\n"
                         :: "r"(dst), "l"(src));
        }
        // B tile: 32 x 128 floats
#pragma unroll
        for (int i = 0; i < 4; i++) {
            int idx = tid + i * 256;
            int r = idx >> 5, c = (idx & 31) * 4;
            uint32_t dst = bs_base + (uint32_t)(buf * B_SZ + r * B_STRIDE + c) * 4u;
            const float* src = Bg + (size_t)(k0 + r) * N + c;
            asm volatile("cp.async.cg.shared.global [%0], [%1], 16;\n"
                         :: "r"(dst), "l"(src));
        }
        asm volatile("cp.async.commit_group;\n");
    };

    issue_loads(0, 0);
    const int KT = Kd >> 5;
    const int fr = lane >> 2;   // 0..7
    const int fc = lane & 3;    // 0..3

    for (int kt = 0; kt < KT; kt++) {
        asm volatile("cp.async.wait_group 0;\n");
        __syncthreads();
        const int cur = kt & 1;
        if (kt + 1 < KT) issue_loads(cur ^ 1, (kt + 1) << 5);

        const float* sA = As + cur * A_SZ;
        const float* sB = Bsm + cur * B_SZ;

#pragma unroll
        for (int kk = 0; kk < 4; kk++) {
            uint32_t af[4][4];
            uint32_t bf[4][2];
#pragma unroll
            for (int mt = 0; mt < 4; mt++) {
                const float* p = sA + (warpM * 64 + mt * 16 + fr) * A_STRIDE + kk * 8 + fc;
                af[mt][0] = f2tf32(p[0]);
                af[mt][1] = f2tf32(p[8 * A_STRIDE]);
                af[mt][2] = f2tf32(p[4]);
                af[mt][3] = f2tf32(p[8 * A_STRIDE + 4]);
            }
#pragma unroll
            for (int nt = 0; nt < 4; nt++) {
                const float* p = sB + (kk * 8 + fc) * B_STRIDE + warpN * 32 + nt * 8 + fr;
                bf[nt][0] = f2tf32(p[0]);
                bf[nt][1] = f2tf32(p[4 * B_STRIDE]);
            }
#pragma unroll
            for (int mt = 0; mt < 4; mt++)
#pragma unroll
                for (int nt = 0; nt < 4; nt++) {
                    asm volatile(
                        "mma.sync.aligned.m16n8k8.row.col.f32.tf32.tf32.f32 "
                        "{%0,%1,%2,%3}, {%4,%5,%6,%7}, {%8,%9}, {%0,%1,%2,%3};\n"
                        : "+f"(acc[mt][nt][0]), "+f"(acc[mt][nt][1]),
                          "+f"(acc[mt][nt][2]), "+f"(acc[mt][nt][3])
                        : "r"(af[mt][0]), "r"(af[mt][1]), "r"(af[mt][2]), "r"(af[mt][3]),
                          "r"(bf[nt][0]), "r"(bf[nt][1]));
                }
        }
        __syncthreads();
    }

    // Epilogue
    float* Cg = C + (size_t)blockIdx.y * 128 * N + (size_t)blockIdx.x * 128;
#pragma unroll
    for (int mt = 0; mt < 4; mt++) {
#pragma unroll
        for (int nt = 0; nt < 4; nt++) {
            int row = warpM * 64 + mt * 16 + fr;
            int col = warpN * 32 + nt * 8 + fc * 2;
            *(float2*)(Cg + (size_t)row * N + col) =
                make_float2(acc[mt][nt][0], acc[mt][nt][1]);
            *(float2*)(Cg + (size_t)(row + 8) * N + col) =
                make_float2(acc[mt][nt][2], acc[mt][nt][3]);
        }
    }
}

// --------------------------- positions from sorted segment ids ---------------
__global__ void pos_kernel(const int* __restrict__ seg, int* __restrict__ pos) {
    int idx = blockIdx.x * blockDim.x + threadIdx.x;
    if (idx >= MTOT) return;
    int b = idx / Tt;
    int t = idx % Tt;
    const int* row = seg + (size_t)b * Tt;
    int s = row[t];
    int lo = 0, hi = t;
    while (lo < hi) {
        int mid = (lo + hi) >> 1;
        if (row[mid] < s) lo = mid + 1; else hi = mid;
    }
    pos[idx] = t - lo;
}

// --------------------------- fused RMSNorm + RoPE (in place) -----------------
__global__ __launch_bounds__(128)
void rms_rope_kernel(float* __restrict__ x, const float* __restrict__ scale,
                     const int* __restrict__ pos, int NH) {
    const int bt = blockIdx.x / NH;
    const int h  = blockIdx.x % NH;
    float* p = x + ((size_t)bt * NH + h) * Kk;

    const int i = threadIdx.x;
    float v = p[i];

    __shared__ float red[4];
    __shared__ float sx[Kk];
    float sq = v * v;
#pragma unroll
    for (int o = 16; o; o >>= 1) sq += __shfl_xor_sync(0xffffffffu, sq, o);
    if ((i & 31) == 0) red[i >> 5] = sq;
    __syncthreads();
    float var = (red[0] + red[1] + red[2] + red[3]) * (1.0f / Kk);
    float xn  = v * rsqrtf(var + EPS) * scale[i];
    sx[i] = xn;
    __syncthreads();

    if (i < Kk / 2) {
        float x1 = sx[i];
        float x2 = sx[i + Kk / 2];
        float pp = (float)pos[bt];
        float inv = expf(-logf(ROPE_BASE) * (2.0f * (float)i / (float)Kk));
        float ang = pp * inv;
        float s, c;
        sincosf(ang, &s, &c);
        p[i]           = x1 * c - x2 * s;
        p[i + Kk / 2]  = x2 * c + x1 * s;
    }
}

// --------------------------- attention: warp per (b,t,h) ---------------------
// Contiguous key window [t - pos[t], t]; float4-vectorized K/V loads.
__global__ __launch_bounds__(256)
void attn_kernel(const float* __restrict__ q, const float* __restrict__ k,
                 const float* __restrict__ v, const int* __restrict__ pos,
                 float* __restrict__ out) {
    const int warp = threadIdx.x >> 5;
    const int lane = threadIdx.x & 31;
    const long gw = (long)blockIdx.x * 8 + warp;
    const int b = (int)(gw / ((long)Tt * Hh));
    const int rem = (int)(gw % ((long)Tt * Hh));
    const int t = rem / Hh;
    const int h = rem % Hh;
    const int g = h / Rr;

    const float4* qp = (const float4*)(q + (((size_t)b * Tt + t) * Hh + h) * Kk);
    const float4 qv = qp[lane];

    const int p  = pos[b * Tt + t];
    const int s0 = t - p;

    float m = -INFINITY, l = 0.f;
    float a0 = 0.f, a1 = 0.f, a2 = 0.f, a3 = 0.f;

    const float* kbase = k + ((size_t)b * Tt * Gg + g) * Kk;
    const float* vbase = v + ((size_t)b * Tt * Gg + g) * Kk;

    for (int s = s0; s <= t; ++s) {
        const float4 kv = *((const float4*)(kbase + (size_t)s * Gg * Kk) + lane);
        float sc = qv.x * kv.x + qv.y * kv.y + qv.z * kv.z + qv.w * kv.w;
#pragma unroll
        for (int o = 16; o; o >>= 1) sc += __shfl_xor_sync(0xffffffffu, sc, o);
        sc *= SOFTMAX_SCALE;

        float mn   = fmaxf(m, sc);
        float corr = __expf(m - mn);
        float pe   = __expf(sc - mn);
        l = l * corr + pe;

        const float4 vv = *((const float4*)(vbase + (size_t)s * Gg * Kk) + lane);
        a0 = a0 * corr + pe * vv.x;
        a1 = a1 * corr + pe * vv.y;
        a2 = a2 * corr + pe * vv.z;
        a3 = a3 * corr + pe * vv.w;
        m = mn;
    }

    float inv = 1.0f / l;
    float4* op = (float4*)(out + (((size_t)b * Tt + t) * Hh + h) * Kk);
    op[lane] = make_float4(a0 * inv, a1 * inv, a2 * inv, a3 * inv);
}

// --------------------------- launch --------------------------------------
extern "C" void kernel_launch(void* const* d_in, const int* in_sizes, int n_in,
                              void* d_out, int out_size) {
    const float* hidden  = (const float*)d_in[0];
    const float* wq      = (const float*)d_in[1];
    const float* wk      = (const float*)d_in[2];
    const float* wv      = (const float*)d_in[3];
    const float* wo      = (const float*)d_in[4];
    const float* q_scale = (const float*)d_in[5];
    const float* k_scale = (const float*)d_in[6];
    const int*   seg     = (const int*)d_in[7];
    float* out = (float*)d_out;

    float *qb, *kb, *vb, *ab;
    int* posb;
    cudaGetSymbolAddress((void**)&qb, g_q);
    cudaGetSymbolAddress((void**)&kb, g_k);
    cudaGetSymbolAddress((void**)&vb, g_v);
    cudaGetSymbolAddress((void**)&ab, g_attn);
    cudaGetSymbolAddress((void**)&posb, g_pos);

    static bool attr_set = false;
    if (!attr_set) {
        cudaFuncSetAttribute(gemm_tf32_kernel,
                             cudaFuncAttributeMaxDynamicSharedMemorySize,
                             GEMM_SMEM_BYTES);
        attr_set = true;
    }

    // 1) QKV projections (tf32 tensor cores)
    {
        dim3 blk(256);
        dim3 grdQ((Hh * Kk) / 128, MTOT / 128);
        gemm_tf32_kernel<<<grdQ, blk, GEMM_SMEM_BYTES>>>(MTOT, Hh * Kk, Dd, hidden, wq, qb);
        dim3 grdK((Gg * Kk) / 128, MTOT / 128);
        gemm_tf32_kernel<<<grdK, blk, GEMM_SMEM_BYTES>>>(MTOT, Gg * Kk, Dd, hidden, wk, kb);
        gemm_tf32_kernel<<<grdK, blk, GEMM_SMEM_BYTES>>>(MTOT, Gg * Kk, Dd, hidden, wv, vb);
    }

    // 2) positions
    pos_kernel<<<(MTOT + 255) / 256, 256>>>(seg, posb);

    // 3) RMSNorm + RoPE (in place) on q and k
    rms_rope_kernel<<<MTOT * Hh, 128>>>(qb, q_scale, posb, Hh);
    rms_rope_kernel<<<MTOT * Gg, 128>>>(kb, k_scale, posb, Gg);

    // 4) attention: one warp per (b,t,h)
    {
        long total_warps = (long)MTOT * Hh;
        int blocks = (int)(total_warps / 8);
        attn_kernel<<<blocks, 256>>>(qb, kb, vb, posb, ab);
    }

    // 5) output projection
    {
        dim3 blk(256);
        dim3 grd(Dd / 128, MTOT / 128);
        gemm_tf32_kernel<<<grd, blk, GEMM_SMEM_BYTES>>>(MTOT, Dd, Hh * Kk, ab, wo, out);
    }
}

// round 7
// speedup vs baseline: 2.0313x; 2.0313x over previous
#include <cuda_runtime.h>
#include <cuda_bf16.h>
#include <math.h>
#include <stdint.h>

// Problem constants
#define Bb 4
#define Tt 2048
#define Dd 2048
#define Hh 16
#define Gg 4
#define Kk 128
#define Rr 4          // H / G
#define EPS 1e-6f
#define ROPE_BASE 10000.0f
#define SOFTMAX_SCALE 0.08838834764831845f  // K^-0.5

#define MTOT (Bb * Tt)          // 8192 rows

// --------------------------- scratch (device globals; no mallocs) ------------
__device__ float g_q[(size_t)MTOT * Hh * Kk];     // 64 MB
__device__ float g_k[(size_t)MTOT * Gg * Kk];     // 16 MB
__device__ float g_v[(size_t)MTOT * Gg * Kk];     // 16 MB
__device__ float g_attn[(size_t)MTOT * Hh * Kk];  // 64 MB
__device__ int   g_pos[MTOT];

__device__ __forceinline__ uint32_t f2tf32(float x) {
    uint32_t u;
    asm("cvt.rna.tf32.f32 %0, %1;" : "=r"(u) : "f"(x));
    return u;
}

#define MMA_TF32(acc, af, b0v, b1v)                                            \
    asm volatile(                                                              \
        "mma.sync.aligned.m16n8k8.row.col.f32.tf32.tf32.f32 "                  \
        "{%0,%1,%2,%3}, {%4,%5,%6,%7}, {%8,%9}, {%0,%1,%2,%3};\n"              \
        : "+f"((acc)[0]), "+f"((acc)[1]), "+f"((acc)[2]), "+f"((acc)[3])       \
        : "r"((af)[0]), "r"((af)[1]), "r"((af)[2]), "r"((af)[3]),              \
          "r"(b0v), "r"(b1v))

// =============================================================================
// TF32 tensor-core GEMM:  C[M,N] = A[M,Kd] @ B[Kd,N]   (all row-major fp32)
// =============================================================================
#define A_STRIDE 36
#define B_STRIDE 136
#define A_SZ (128 * A_STRIDE)
#define B_SZ (32 * B_STRIDE)
#define GEMM_SMEM_BYTES ((2 * A_SZ + 2 * B_SZ) * 4)   // 71680 B

__global__ __launch_bounds__(256)
void gemm_tf32_kernel(int M, int N, int Kd,
                      const float* __restrict__ A,
                      const float* __restrict__ B,
                      float* __restrict__ C) {
    extern __shared__ float sm[];
    float* As = sm;               // [2][128][A_STRIDE]
    float* Bsm = sm + 2 * A_SZ;   // [2][32][B_STRIDE]

    const int tid  = threadIdx.x;
    const int lane = tid & 31;
    const int wid  = tid >> 5;
    const int warpM = wid & 1;
    const int warpN = wid >> 1;

    const float* Ag = A + (size_t)blockIdx.y * 128 * Kd;
    const float* Bg = B + (size_t)blockIdx.x * 128;

    const uint32_t as_base = (uint32_t)__cvta_generic_to_shared(As);
    const uint32_t bs_base = (uint32_t)__cvta_generic_to_shared(Bsm);

    float acc[4][4][4];
#pragma unroll
    for (int i = 0; i < 4; i++)
#pragma unroll
        for (int j = 0; j < 4; j++)
#pragma unroll
            for (int r = 0; r < 4; r++) acc[i][j][r] = 0.f;

    auto issue_loads = [&](int buf, int k0) {
#pragma unroll
        for (int i = 0; i < 4; i++) {
            int idx = tid + i * 256;
            int r = idx >> 3, c = (idx & 7) * 4;
            uint32_t dst = as_base + (uint32_t)(buf * A_SZ + r * A_STRIDE + c) * 4u;
            const float* src = Ag + (size_t)r * Kd + k0 + c;
            asm volatile("cp.async.cg.shared.global [%0], [%1], 16;\n"
                         :: "r"(dst), "l"(src));
        }
#pragma unroll
        for (int i = 0; i < 4; i++) {
            int idx = tid + i * 256;
            int r = idx >> 5, c = (idx & 31) * 4;
            uint32_t dst = bs_base + (uint32_t)(buf * B_SZ + r * B_STRIDE + c) * 4u;
            const float* src = Bg + (size_t)(k0 + r) * N + c;
            asm volatile("cp.async.cg.shared.global [%0], [%1], 16;\n"
                         :: "r"(dst), "l"(src));
        }
        asm volatile("cp.async.commit_group;\n");
    };

    issue_loads(0, 0);
    const int KT = Kd >> 5;
    const int fr = lane >> 2;
    const int fc = lane & 3;

    for (int kt = 0; kt < KT; kt++) {
        asm volatile("cp.async.wait_group 0;\n");
        __syncthreads();
        const int cur = kt & 1;
        if (kt + 1 < KT) issue_loads(cur ^ 1, (kt + 1) << 5);

        const float* sA = As + cur * A_SZ;
        const float* sB = Bsm + cur * B_SZ;

#pragma unroll
        for (int kk = 0; kk < 4; kk++) {
            uint32_t af[4][4];
            uint32_t bfr[4][2];
#pragma unroll
            for (int mt = 0; mt < 4; mt++) {
                const float* p = sA + (warpM * 64 + mt * 16 + fr) * A_STRIDE + kk * 8 + fc;
                af[mt][0] = f2tf32(p[0]);
                af[mt][1] = f2tf32(p[8 * A_STRIDE]);
                af[mt][2] = f2tf32(p[4]);
                af[mt][3] = f2tf32(p[8 * A_STRIDE + 4]);
            }
#pragma unroll
            for (int nt = 0; nt < 4; nt++) {
                const float* p = sB + (kk * 8 + fc) * B_STRIDE + warpN * 32 + nt * 8 + fr;
                bfr[nt][0] = f2tf32(p[0]);
                bfr[nt][1] = f2tf32(p[4 * B_STRIDE]);
            }
#pragma unroll
            for (int mt = 0; mt < 4; mt++)
#pragma unroll
                for (int nt = 0; nt < 4; nt++)
                    MMA_TF32(acc[mt][nt], af[mt], bfr[nt][0], bfr[nt][1]);
        }
        __syncthreads();
    }

    float* Cg = C + (size_t)blockIdx.y * 128 * N + (size_t)blockIdx.x * 128;
#pragma unroll
    for (int mt = 0; mt < 4; mt++) {
#pragma unroll
        for (int nt = 0; nt < 4; nt++) {
            int row = warpM * 64 + mt * 16 + fr;
            int col = warpN * 32 + nt * 8 + fc * 2;
            *(float2*)(Cg + (size_t)row * N + col) =
                make_float2(acc[mt][nt][0], acc[mt][nt][1]);
            *(float2*)(Cg + (size_t)(row + 8) * N + col) =
                make_float2(acc[mt][nt][2], acc[mt][nt][3]);
        }
    }
}

// --------------------------- positions from sorted segment ids ---------------
__global__ void pos_kernel(const int* __restrict__ seg, int* __restrict__ pos) {
    int idx = blockIdx.x * blockDim.x + threadIdx.x;
    if (idx >= MTOT) return;
    int b = idx / Tt;
    int t = idx % Tt;
    const int* row = seg + (size_t)b * Tt;
    int s = row[t];
    int lo = 0, hi = t;
    while (lo < hi) {
        int mid = (lo + hi) >> 1;
        if (row[mid] < s) lo = mid + 1; else hi = mid;
    }
    pos[idx] = t - lo;
}

// --------------------------- fused RMSNorm + RoPE (in place) -----------------
__global__ __launch_bounds__(128)
void rms_rope_kernel(float* __restrict__ x, const float* __restrict__ scale,
                     const int* __restrict__ pos, int NH) {
    const int bt = blockIdx.x / NH;
    const int h  = blockIdx.x % NH;
    float* p = x + ((size_t)bt * NH + h) * Kk;

    const int i = threadIdx.x;
    float v = p[i];

    __shared__ float red[4];
    __shared__ float sx[Kk];
    float sq = v * v;
#pragma unroll
    for (int o = 16; o; o >>= 1) sq += __shfl_xor_sync(0xffffffffu, sq, o);
    if ((i & 31) == 0) red[i >> 5] = sq;
    __syncthreads();
    float var = (red[0] + red[1] + red[2] + red[3]) * (1.0f / Kk);
    float xn  = v * rsqrtf(var + EPS) * scale[i];
    sx[i] = xn;
    __syncthreads();

    if (i < Kk / 2) {
        float x1 = sx[i];
        float x2 = sx[i + Kk / 2];
        float pp = (float)pos[bt];
        float inv = expf(-logf(ROPE_BASE) * (2.0f * (float)i / (float)Kk));
        float ang = pp * inv;
        float s, c;
        sincosf(ang, &s, &c);
        p[i]           = x1 * c - x2 * s;
        p[i + Kk / 2]  = x2 * c + x1 * s;
    }
}

// =============================================================================
// Flash attention (tf32 tensor cores).
// Block = (qtile of 32 queries, g, b). M = 128 rows = 4 heads x 32 queries.
// 8 warps; warp w owns rows [16w,16w+16): head h_local = w/2, queries
// q_base=(w&1)*16 .. +16. Key tiles of 32 staged in smem (cp.async dbl-buffer).
// Valid key window per query t: [t - pos[t], t] (contiguous; sorted segments).
// =============================================================================
#define KV_STRIDE 132
#define KV_SZ (32 * KV_STRIDE)          // 4224 floats per buffer
#define P_STRIDE 36
#define FA_SMEM_BYTES ((4 * KV_SZ + 128 * P_STRIDE) * 4)   // 86016 B

__device__ __forceinline__ float qmax2(float x) {
    x = fmaxf(x, __shfl_xor_sync(0xffffffffu, x, 1));
    x = fmaxf(x, __shfl_xor_sync(0xffffffffu, x, 2));
    return x;
}
__device__ __forceinline__ float qsum2(float x) {
    x += __shfl_xor_sync(0xffffffffu, x, 1);
    x += __shfl_xor_sync(0xffffffffu, x, 2);
    return x;
}

__global__ __launch_bounds__(256)
void fa_kernel(const float* __restrict__ q, const float* __restrict__ k,
               const float* __restrict__ v, const int* __restrict__ pos,
               float* __restrict__ out) {
    extern __shared__ float fsm[];
    float* Ks = fsm;                    // [2][KV_SZ]
    float* Vs = fsm + 2 * KV_SZ;        // [2][KV_SZ]
    float* Ps = fsm + 4 * KV_SZ;        // [128][P_STRIDE] (tf32 bit patterns)

    const int tid  = threadIdx.x;
    const int lane = tid & 31;
    const int w    = tid >> 5;
    const int t0   = blockIdx.x * 32;
    const int g    = blockIdx.y;
    const int b    = blockIdx.z;

    const int h_local = w >> 1;
    const int q_base  = (w & 1) * 16;
    const int h = g * Rr + h_local;

    const int fr = lane >> 2;  // 0..7
    const int fc = lane & 3;   // 0..3

    const int r0 = q_base + fr;         // local query 0..31
    const int t_r0 = t0 + r0;
    const int t_r1 = t_r0 + 8;
    const int pos0 = pos[b * Tt + t_r0];
    const int pos1 = pos[b * Tt + t_r1];
    const int w0lo = t_r0 - pos0;
    const int w1lo = t_r1 - pos1;

    // ---- Q fragments (tf32), K=128 -> 16 k-chunks of 8 ----
    uint32_t qf[16][4];
    {
        const float* q0p = q + (((size_t)b * Tt + t_r0) * Hh + h) * Kk;
        const float* q1p = q + (((size_t)b * Tt + t_r1) * Hh + h) * Kk;
#pragma unroll
        for (int kc = 0; kc < 16; kc++) {
            qf[kc][0] = f2tf32(q0p[kc * 8 + fc]);
            qf[kc][1] = f2tf32(q1p[kc * 8 + fc]);
            qf[kc][2] = f2tf32(q0p[kc * 8 + fc + 4]);
            qf[kc][3] = f2tf32(q1p[kc * 8 + fc + 4]);
        }
    }

    float oa[16][4];
#pragma unroll
    for (int i = 0; i < 16; i++)
#pragma unroll
        for (int j = 0; j < 4; j++) oa[i][j] = 0.f;
    float m0 = -1e30f, m1 = -1e30f, l0 = 0.f, l1 = 0.f;

    const int win_lo  = t0 - pos[b * Tt + t0];     // earliest window start in tile
    const int s_begin = win_lo & ~31;
    const int n_tiles = ((t0 + 31 - s_begin) >> 5) + 1;

    const uint32_t ks_base = (uint32_t)__cvta_generic_to_shared(Ks);
    const uint32_t vs_base = (uint32_t)__cvta_generic_to_shared(Vs);
    const float* kg = k + ((size_t)b * Tt * Gg + g) * Kk;
    const float* vg = v + ((size_t)b * Tt * Gg + g) * Kk;

    auto load_tile = [&](int buf, int s_tile) {
#pragma unroll
        for (int i = 0; i < 4; i++) {
            int idx = tid + i * 256;
            int r = idx >> 5, c = (idx & 31) * 4;   // 32 rows x 32 float4
            uint32_t dst = ks_base + (uint32_t)(buf * KV_SZ + r * KV_STRIDE + c) * 4u;
            const float* src = kg + (size_t)(s_tile + r) * Gg * Kk + c;
            asm volatile("cp.async.cg.shared.global [%0], [%1], 16;\n"
                         :: "r"(dst), "l"(src));
        }
#pragma unroll
        for (int i = 0; i < 4; i++) {
            int idx = tid + i * 256;
            int r = idx >> 5, c = (idx & 31) * 4;
            uint32_t dst = vs_base + (uint32_t)(buf * KV_SZ + r * KV_STRIDE + c) * 4u;
            const float* src = vg + (size_t)(s_tile + r) * Gg * Kk + c;
            asm volatile("cp.async.cg.shared.global [%0], [%1], 16;\n"
                         :: "r"(dst), "l"(src));
        }
        asm volatile("cp.async.commit_group;\n");
    };

    load_tile(0, s_begin);

    for (int it = 0; it < n_tiles; it++) {
        const int s_tile = s_begin + it * 32;
        asm volatile("cp.async.wait_group 0;\n");
        __syncthreads();
        const int cur = it & 1;
        if (it + 1 < n_tiles) load_tile(cur ^ 1, s_tile + 32);

        // ---- scores S[16,32] ----
        float sc[4][4];
#pragma unroll
        for (int nt = 0; nt < 4; nt++)
#pragma unroll
            for (int i = 0; i < 4; i++) sc[nt][i] = 0.f;

        const float* Kb = Ks + cur * KV_SZ;
#pragma unroll
        for (int nt = 0; nt < 4; nt++) {
            const float* kp = Kb + (nt * 8 + fr) * KV_STRIDE + fc;
#pragma unroll
            for (int kc = 0; kc < 16; kc++) {
                uint32_t b0 = f2tf32(kp[kc * 8]);
                uint32_t b1 = f2tf32(kp[kc * 8 + 4]);
                MMA_TF32(sc[nt], qf[kc], b0, b1);
            }
        }

        // ---- mask + online softmax ----
        float x[4][4];
        float rm0 = -1e30f, rm1 = -1e30f;
#pragma unroll
        for (int nt = 0; nt < 4; nt++) {
            int s_b = s_tile + nt * 8 + fc * 2;
            x[nt][0] = (s_b     >= w0lo && s_b     <= t_r0) ? sc[nt][0] * SOFTMAX_SCALE : -1e30f;
            x[nt][1] = (s_b + 1 >= w0lo && s_b + 1 <= t_r0) ? sc[nt][1] * SOFTMAX_SCALE : -1e30f;
            x[nt][2] = (s_b     >= w1lo && s_b     <= t_r1) ? sc[nt][2] * SOFTMAX_SCALE : -1e30f;
            x[nt][3] = (s_b + 1 >= w1lo && s_b + 1 <= t_r1) ? sc[nt][3] * SOFTMAX_SCALE : -1e30f;
            rm0 = fmaxf(rm0, fmaxf(x[nt][0], x[nt][1]));
            rm1 = fmaxf(rm1, fmaxf(x[nt][2], x[nt][3]));
        }
        rm0 = qmax2(rm0);
        rm1 = qmax2(rm1);
        const float mn0 = fmaxf(m0, rm0);
        const float mn1 = fmaxf(m1, rm1);
        const float corr0 = __expf(m0 - mn0);
        const float corr1 = __expf(m1 - mn1);

        __syncwarp();
        float rs0 = 0.f, rs1 = 0.f;
        float* Pp0 = Ps + (w * 16 + fr) * P_STRIDE + fc * 2;
        float* Pp1 = Pp0 + 8 * P_STRIDE;
#pragma unroll
        for (int nt = 0; nt < 4; nt++) {
            float p00 = (x[nt][0] > -1e29f) ? __expf(x[nt][0] - mn0) : 0.f;
            float p01 = (x[nt][1] > -1e29f) ? __expf(x[nt][1] - mn0) : 0.f;
            float p10 = (x[nt][2] > -1e29f) ? __expf(x[nt][2] - mn1) : 0.f;
            float p11 = (x[nt][3] > -1e29f) ? __expf(x[nt][3] - mn1) : 0.f;
            rs0 += p00 + p01;
            rs1 += p10 + p11;
            Pp0[nt * 8]     = __uint_as_float(f2tf32(p00));
            Pp0[nt * 8 + 1] = __uint_as_float(f2tf32(p01));
            Pp1[nt * 8]     = __uint_as_float(f2tf32(p10));
            Pp1[nt * 8 + 1] = __uint_as_float(f2tf32(p11));
        }
        l0 = l0 * corr0 + qsum2(rs0);
        l1 = l1 * corr1 + qsum2(rs1);
        m0 = mn0;
        m1 = mn1;

#pragma unroll
        for (int nt = 0; nt < 16; nt++) {
            oa[nt][0] *= corr0;
            oa[nt][1] *= corr0;
            oa[nt][2] *= corr1;
            oa[nt][3] *= corr1;
        }
        __syncwarp();

        // ---- P fragments ----
        uint32_t pa[4][4];
        const float* Pr = Ps + (w * 16 + fr) * P_STRIDE + fc;
#pragma unroll
        for (int kc = 0; kc < 4; kc++) {
            pa[kc][0] = __float_as_uint(Pr[kc * 8]);
            pa[kc][1] = __float_as_uint(Pr[8 * P_STRIDE + kc * 8]);
            pa[kc][2] = __float_as_uint(Pr[kc * 8 + 4]);
            pa[kc][3] = __float_as_uint(Pr[8 * P_STRIDE + kc * 8 + 4]);
        }

        // ---- O += P @ V ----
        const float* Vb = Vs + cur * KV_SZ;
#pragma unroll
        for (int nt = 0; nt < 16; nt++) {
            const float* vp = Vb + fc * KV_STRIDE + nt * 8 + fr;
#pragma unroll
            for (int kc = 0; kc < 4; kc++) {
                uint32_t b0 = f2tf32(vp[kc * 8 * KV_STRIDE]);
                uint32_t b1 = f2tf32(vp[(kc * 8 + 4) * KV_STRIDE]);
                MMA_TF32(oa[nt], pa[kc], b0, b1);
            }
        }
        __syncwarp();
    }

    // ---- epilogue ----
    const float inv0 = 1.0f / l0;
    const float inv1 = 1.0f / l1;
    float* o0 = out + (((size_t)b * Tt + t_r0) * Hh + h) * Kk;
    float* o1 = out + (((size_t)b * Tt + t_r1) * Hh + h) * Kk;
#pragma unroll
    for (int nt = 0; nt < 16; nt++) {
        int d = nt * 8 + fc * 2;
        *(float2*)(o0 + d) = make_float2(oa[nt][0] * inv0, oa[nt][1] * inv0);
        *(float2*)(o1 + d) = make_float2(oa[nt][2] * inv1, oa[nt][3] * inv1);
    }
}

// --------------------------- launch --------------------------------------
extern "C" void kernel_launch(void* const* d_in, const int* in_sizes, int n_in,
                              void* d_out, int out_size) {
    const float* hidden  = (const float*)d_in[0];
    const float* wq      = (const float*)d_in[1];
    const float* wk      = (const float*)d_in[2];
    const float* wv      = (const float*)d_in[3];
    const float* wo      = (const float*)d_in[4];
    const float* q_scale = (const float*)d_in[5];
    const float* k_scale = (const float*)d_in[6];
    const int*   seg     = (const int*)d_in[7];
    float* out = (float*)d_out;

    float *qb, *kb, *vb, *ab;
    int* posb;
    cudaGetSymbolAddress((void**)&qb, g_q);
    cudaGetSymbolAddress((void**)&kb, g_k);
    cudaGetSymbolAddress((void**)&vb, g_v);
    cudaGetSymbolAddress((void**)&ab, g_attn);
    cudaGetSymbolAddress((void**)&posb, g_pos);

    static bool attr_set = false;
    if (!attr_set) {
        cudaFuncSetAttribute(gemm_tf32_kernel,
                             cudaFuncAttributeMaxDynamicSharedMemorySize,
                             GEMM_SMEM_BYTES);
        cudaFuncSetAttribute(fa_kernel,
                             cudaFuncAttributeMaxDynamicSharedMemorySize,
                             FA_SMEM_BYTES);
        attr_set = true;
    }

    // 1) QKV projections (tf32 tensor cores)
    {
        dim3 blk(256);
        dim3 grdQ((Hh * Kk) / 128, MTOT / 128);
        gemm_tf32_kernel<<<grdQ, blk, GEMM_SMEM_BYTES>>>(MTOT, Hh * Kk, Dd, hidden, wq, qb);
        dim3 grdK((Gg * Kk) / 128, MTOT / 128);
        gemm_tf32_kernel<<<grdK, blk, GEMM_SMEM_BYTES>>>(MTOT, Gg * Kk, Dd, hidden, wk, kb);
        gemm_tf32_kernel<<<grdK, blk, GEMM_SMEM_BYTES>>>(MTOT, Gg * Kk, Dd, hidden, wv, vb);
    }

    // 2) positions
    pos_kernel<<<(MTOT + 255) / 256, 256>>>(seg, posb);

    // 3) RMSNorm + RoPE (in place) on q and k
    rms_rope_kernel<<<MTOT * Hh, 128>>>(qb, q_scale, posb, Hh);
    rms_rope_kernel<<<MTOT * Gg, 128>>>(kb, k_scale, posb, Gg);

    // 4) flash attention
    {
        dim3 grd(Tt / 32, Gg, Bb);
        fa_kernel<<<grd, 256, FA_SMEM_BYTES>>>(qb, kb, vb, posb, ab);
    }

    // 5) output projection
    {
        dim3 blk(256);
        dim3 grd(Dd / 128, MTOT / 128);
        gemm_tf32_kernel<<<grd, blk, GEMM_SMEM_BYTES>>>(MTOT, Dd, Hh * Kk, ab, wo, out);
    }
}

// round 8
// speedup vs baseline: 3.1318x; 1.5417x over previous
#include <cuda_runtime.h>
#include <cuda_fp16.h>
#include <cuda_bf16.h>
#include <math.h>
#include <stdint.h>

// Problem constants
#define Bb 4
#define Tt 2048
#define Dd 2048
#define Hh 16
#define Gg 4
#define Kk 128
#define Rr 4          // H / G
#define EPS 1e-6f
#define ROPE_BASE 10000.0f
#define SOFTMAX_SCALE 0.08838834764831845f  // K^-0.5

#define MTOT (Bb * Tt)          // 8192 rows

// --------------------------- scratch (device globals; no mallocs) ------------
__device__ float g_q[(size_t)MTOT * Hh * Kk];     // 64 MB
__device__ float g_k[(size_t)MTOT * Gg * Kk];     // 16 MB
__device__ float g_v[(size_t)MTOT * Gg * Kk];     // 16 MB
__device__ float g_attn[(size_t)MTOT * Hh * Kk];  // 64 MB
__device__ int   g_pos[MTOT];
// fp16 copies for tensor-core GEMMs
__device__ __half g_h16[(size_t)MTOT * Dd];       // 32 MB
__device__ __half g_wq16[(size_t)Dd * Hh * Kk];   // 8 MB
__device__ __half g_wk16[(size_t)Dd * Gg * Kk];   // 2 MB
__device__ __half g_wv16[(size_t)Dd * Gg * Kk];   // 2 MB
__device__ __half g_wo16[(size_t)Hh * Kk * Dd];   // 8 MB
__device__ __half g_a16[(size_t)MTOT * Hh * Kk];  // 32 MB

__device__ __forceinline__ uint32_t f2tf32(float x) {
    uint32_t u;
    asm("cvt.rna.tf32.f32 %0, %1;" : "=r"(u) : "f"(x));
    return u;
}

#define MMA_TF32(acc, af, b0v, b1v)                                            \
    asm volatile(                                                              \
        "mma.sync.aligned.m16n8k8.row.col.f32.tf32.tf32.f32 "                  \
        "{%0,%1,%2,%3}, {%4,%5,%6,%7}, {%8,%9}, {%0,%1,%2,%3};\n"              \
        : "+f"((acc)[0]), "+f"((acc)[1]), "+f"((acc)[2]), "+f"((acc)[3])       \
        : "r"((af)[0]), "r"((af)[1]), "r"((af)[2]), "r"((af)[3]),              \
          "r"(b0v), "r"(b1v))

#define MMA_F16(acc, af, b0v, b1v)                                             \
    asm volatile(                                                              \
        "mma.sync.aligned.m16n8k16.row.col.f32.f16.f16.f32 "                   \
        "{%0,%1,%2,%3}, {%4,%5,%6,%7}, {%8,%9}, {%0,%1,%2,%3};\n"              \
        : "+f"((acc)[0]), "+f"((acc)[1]), "+f"((acc)[2]), "+f"((acc)[3])       \
        : "r"((af)[0]), "r"((af)[1]), "r"((af)[2]), "r"((af)[3]),              \
          "r"(b0v), "r"(b1v))

// --------------------------- f32 -> f16 convert ------------------------------
__global__ __launch_bounds__(256)
void f2h_kernel(const float* __restrict__ src, __half* __restrict__ dst, int n) {
    int i = (blockIdx.x * blockDim.x + threadIdx.x) * 8;
    if (i >= n) return;
    float4 x = *(const float4*)(src + i);
    float4 y = *(const float4*)(src + i + 4);
    __half2 h0 = __floats2half2_rn(x.x, x.y);
    __half2 h1 = __floats2half2_rn(x.z, x.w);
    __half2 h2 = __floats2half2_rn(y.x, y.y);
    __half2 h3 = __floats2half2_rn(y.z, y.w);
    uint4 o;
    o.x = *(uint32_t*)&h0; o.y = *(uint32_t*)&h1;
    o.z = *(uint32_t*)&h2; o.w = *(uint32_t*)&h3;
    *(uint4*)(dst + i) = o;
}

// =============================================================================
// FP16 tensor-core GEMM:  C[M,N](f32) = A[M,Kd](f16) @ B[Kd,N](f16)
// CTA 128x128, BK=32, 256 thr, 8 warps (2x4), mma.m16n8k16 + ldmatrix.
// A smem stride 40 halves, B stride 136 halves: conflict-free ldmatrix phases.
// =============================================================================
#define HA_STR 40
#define HB_STR 136

__global__ __launch_bounds__(256)
void hgemm_kernel(int M, int N, int Kd,
                  const __half* __restrict__ A,
                  const __half* __restrict__ B,
                  float* __restrict__ C) {
    __shared__ __half As[2][128][HA_STR];
    __shared__ __half Bs[2][32][HB_STR];

    const int tid  = threadIdx.x;
    const int lane = tid & 31;
    const int wid  = tid >> 5;
    const int warpM = wid & 1;    // 64 rows
    const int warpN = wid >> 1;   // 32 cols

    const __half* Ag = A + (size_t)blockIdx.y * 128 * Kd;
    const __half* Bg = B + (size_t)blockIdx.x * 128;

    float acc[4][4][4];
#pragma unroll
    for (int i = 0; i < 4; i++)
#pragma unroll
        for (int j = 0; j < 4; j++)
#pragma unroll
            for (int r = 0; r < 4; r++) acc[i][j][r] = 0.f;

    auto issue_loads = [&](int buf, int k0) {
        // A tile 128x32 halves: 512 chunks of 8 halves, 2 per thread
#pragma unroll
        for (int i = 0; i < 2; i++) {
            int idx = tid + i * 256;
            int r = idx >> 2, c = (idx & 3) * 8;
            uint32_t dst = (uint32_t)__cvta_generic_to_shared(&As[buf][r][c]);
            const __half* src = Ag + (size_t)r * Kd + k0 + c;
            asm volatile("cp.async.cg.shared.global [%0], [%1], 16;\n"
                         :: "r"(dst), "l"(src));
        }
        // B tile 32x128 halves
#pragma unroll
        for (int i = 0; i < 2; i++) {
            int idx = tid + i * 256;
            int r = idx >> 4, c = (idx & 15) * 8;
            uint32_t dst = (uint32_t)__cvta_generic_to_shared(&Bs[buf][r][c]);
            const __half* src = Bg + (size_t)(k0 + r) * N + c;
            asm volatile("cp.async.cg.shared.global [%0], [%1], 16;\n"
                         :: "r"(dst), "l"(src));
        }
        asm volatile("cp.async.commit_group;\n");
    };

    issue_loads(0, 0);
    const int KT = Kd >> 5;
    const int fr = lane >> 2;
    const int fc = lane & 3;
    const int grp = lane >> 3;          // 0..3
    const int gr8 = lane & 7;

    for (int kt = 0; kt < KT; kt++) {
        asm volatile("cp.async.wait_group 0;\n");
        __syncthreads();
        const int cur = kt & 1;
        if (kt + 1 < KT) issue_loads(cur ^ 1, (kt + 1) << 5);

#pragma unroll
        for (int kc = 0; kc < 2; kc++) {
            uint32_t af[4][4];
            uint32_t bf[4][2];
#pragma unroll
            for (int mt = 0; mt < 4; mt++) {
                int row = warpM * 64 + mt * 16 + (grp & 1) * 8 + gr8;
                int col = kc * 16 + (grp >> 1) * 8;
                uint32_t addr = (uint32_t)__cvta_generic_to_shared(&As[cur][row][col]);
                asm volatile("ldmatrix.sync.aligned.m8n8.x4.shared.b16 "
                             "{%0,%1,%2,%3}, [%4];\n"
                             : "=r"(af[mt][0]), "=r"(af[mt][1]),
                               "=r"(af[mt][2]), "=r"(af[mt][3])
                             : "r"(addr));
            }
#pragma unroll
            for (int np = 0; np < 2; np++) {
                int krow = kc * 16 + (grp & 1) * 8 + gr8;
                int ncol = warpN * 32 + np * 16 + (grp >> 1) * 8;
                uint32_t addr = (uint32_t)__cvta_generic_to_shared(&Bs[cur][krow][ncol]);
                asm volatile("ldmatrix.sync.aligned.m8n8.x4.trans.shared.b16 "
                             "{%0,%1,%2,%3}, [%4];\n"
                             : "=r"(bf[np * 2][0]), "=r"(bf[np * 2][1]),
                               "=r"(bf[np * 2 + 1][0]), "=r"(bf[np * 2 + 1][1])
                             : "r"(addr));
            }
#pragma unroll
            for (int mt = 0; mt < 4; mt++)
#pragma unroll
                for (int nt = 0; nt < 4; nt++)
                    MMA_F16(acc[mt][nt], af[mt], bf[nt][0], bf[nt][1]);
        }
        __syncthreads();
    }

    float* Cg = C + (size_t)blockIdx.y * 128 * N + (size_t)blockIdx.x * 128;
#pragma unroll
    for (int mt = 0; mt < 4; mt++) {
#pragma unroll
        for (int nt = 0; nt < 4; nt++) {
            int row = warpM * 64 + mt * 16 + fr;
            int col = warpN * 32 + nt * 8 + fc * 2;
            *(float2*)(Cg + (size_t)row * N + col) =
                make_float2(acc[mt][nt][0], acc[mt][nt][1]);
            *(float2*)(Cg + (size_t)(row + 8) * N + col) =
                make_float2(acc[mt][nt][2], acc[mt][nt][3]);
        }
    }
}

// --------------------------- positions from sorted segment ids ---------------
__global__ void pos_kernel(const int* __restrict__ seg, int* __restrict__ pos) {
    int idx = blockIdx.x * blockDim.x + threadIdx.x;
    if (idx >= MTOT) return;
    int b = idx / Tt;
    int t = idx % Tt;
    const int* row = seg + (size_t)b * Tt;
    int s = row[t];
    int lo = 0, hi = t;
    while (lo < hi) {
        int mid = (lo + hi) >> 1;
        if (row[mid] < s) lo = mid + 1; else hi = mid;
    }
    pos[idx] = t - lo;
}

// --------------------------- fused RMSNorm + RoPE (in place) -----------------
__global__ __launch_bounds__(128)
void rms_rope_kernel(float* __restrict__ x, const float* __restrict__ scale,
                     const int* __restrict__ pos, int NH) {
    const int bt = blockIdx.x / NH;
    const int h  = blockIdx.x % NH;
    float* p = x + ((size_t)bt * NH + h) * Kk;

    const int i = threadIdx.x;
    float v = p[i];

    __shared__ float red[4];
    __shared__ float sx[Kk];
    float sq = v * v;
#pragma unroll
    for (int o = 16; o; o >>= 1) sq += __shfl_xor_sync(0xffffffffu, sq, o);
    if ((i & 31) == 0) red[i >> 5] = sq;
    __syncthreads();
    float var = (red[0] + red[1] + red[2] + red[3]) * (1.0f / Kk);
    float xn  = v * rsqrtf(var + EPS) * scale[i];
    sx[i] = xn;
    __syncthreads();

    if (i < Kk / 2) {
        float x1 = sx[i];
        float x2 = sx[i + Kk / 2];
        float pp = (float)pos[bt];
        float inv = expf(-logf(ROPE_BASE) * (2.0f * (float)i / (float)Kk));
        float ang = pp * inv;
        float s, c;
        sincosf(ang, &s, &c);
        p[i]           = x1 * c - x2 * s;
        p[i + Kk / 2]  = x2 * c + x1 * s;
    }
}

// =============================================================================
// Flash attention (tf32 tensor cores), unchanged from R6.
// =============================================================================
#define KV_STRIDE 132
#define KV_SZ (32 * KV_STRIDE)
#define P_STRIDE 36
#define FA_SMEM_BYTES ((4 * KV_SZ + 128 * P_STRIDE) * 4)   // 86016 B

__device__ __forceinline__ float qmax2(float x) {
    x = fmaxf(x, __shfl_xor_sync(0xffffffffu, x, 1));
    x = fmaxf(x, __shfl_xor_sync(0xffffffffu, x, 2));
    return x;
}
__device__ __forceinline__ float qsum2(float x) {
    x += __shfl_xor_sync(0xffffffffu, x, 1);
    x += __shfl_xor_sync(0xffffffffu, x, 2);
    return x;
}

__global__ __launch_bounds__(256)
void fa_kernel(const float* __restrict__ q, const float* __restrict__ k,
               const float* __restrict__ v, const int* __restrict__ pos,
               float* __restrict__ out) {
    extern __shared__ float fsm[];
    float* Ks = fsm;
    float* Vs = fsm + 2 * KV_SZ;
    float* Ps = fsm + 4 * KV_SZ;

    const int tid  = threadIdx.x;
    const int lane = tid & 31;
    const int w    = tid >> 5;
    const int t0   = blockIdx.x * 32;
    const int g    = blockIdx.y;
    const int b    = blockIdx.z;

    const int h_local = w >> 1;
    const int q_base  = (w & 1) * 16;
    const int h = g * Rr + h_local;

    const int fr = lane >> 2;
    const int fc = lane & 3;

    const int r0 = q_base + fr;
    const int t_r0 = t0 + r0;
    const int t_r1 = t_r0 + 8;
    const int pos0 = pos[b * Tt + t_r0];
    const int pos1 = pos[b * Tt + t_r1];
    const int w0lo = t_r0 - pos0;
    const int w1lo = t_r1 - pos1;

    uint32_t qf[16][4];
    {
        const float* q0p = q + (((size_t)b * Tt + t_r0) * Hh + h) * Kk;
        const float* q1p = q + (((size_t)b * Tt + t_r1) * Hh + h) * Kk;
#pragma unroll
        for (int kc = 0; kc < 16; kc++) {
            qf[kc][0] = f2tf32(q0p[kc * 8 + fc]);
            qf[kc][1] = f2tf32(q1p[kc * 8 + fc]);
            qf[kc][2] = f2tf32(q0p[kc * 8 + fc + 4]);
            qf[kc][3] = f2tf32(q1p[kc * 8 + fc + 4]);
        }
    }

    float oa[16][4];
#pragma unroll
    for (int i = 0; i < 16; i++)
#pragma unroll
        for (int j = 0; j < 4; j++) oa[i][j] = 0.f;
    float m0 = -1e30f, m1 = -1e30f, l0 = 0.f, l1 = 0.f;

    const int win_lo  = t0 - pos[b * Tt + t0];
    const int s_begin = win_lo & ~31;
    const int n_tiles = ((t0 + 31 - s_begin) >> 5) + 1;

    const uint32_t ks_base = (uint32_t)__cvta_generic_to_shared(Ks);
    const uint32_t vs_base = (uint32_t)__cvta_generic_to_shared(Vs);
    const float* kg = k + ((size_t)b * Tt * Gg + g) * Kk;
    const float* vg = v + ((size_t)b * Tt * Gg + g) * Kk;

    auto load_tile = [&](int buf, int s_tile) {
#pragma unroll
        for (int i = 0; i < 4; i++) {
            int idx = tid + i * 256;
            int r = idx >> 5, c = (idx & 31) * 4;
            uint32_t dst = ks_base + (uint32_t)(buf * KV_SZ + r * KV_STRIDE + c) * 4u;
            const float* src = kg + (size_t)(s_tile + r) * Gg * Kk + c;
            asm volatile("cp.async.cg.shared.global [%0], [%1], 16;\n"
                         :: "r"(dst), "l"(src));
        }
#pragma unroll
        for (int i = 0; i < 4; i++) {
            int idx = tid + i * 256;
            int r = idx >> 5, c = (idx & 31) * 4;
            uint32_t dst = vs_base + (uint32_t)(buf * KV_SZ + r * KV_STRIDE + c) * 4u;
            const float* src = vg + (size_t)(s_tile + r) * Gg * Kk + c;
            asm volatile("cp.async.cg.shared.global [%0], [%1], 16;\n"
                         :: "r"(dst), "l"(src));
        }
        asm volatile("cp.async.commit_group;\n");
    };

    load_tile(0, s_begin);

    for (int it = 0; it < n_tiles; it++) {
        const int s_tile = s_begin + it * 32;
        asm volatile("cp.async.wait_group 0;\n");
        __syncthreads();
        const int cur = it & 1;
        if (it + 1 < n_tiles) load_tile(cur ^ 1, s_tile + 32);

        float sc[4][4];
#pragma unroll
        for (int nt = 0; nt < 4; nt++)
#pragma unroll
            for (int i = 0; i < 4; i++) sc[nt][i] = 0.f;

        const float* Kb = Ks + cur * KV_SZ;
#pragma unroll
        for (int nt = 0; nt < 4; nt++) {
            const float* kp = Kb + (nt * 8 + fr) * KV_STRIDE + fc;
#pragma unroll
            for (int kc = 0; kc < 16; kc++) {
                uint32_t b0 = f2tf32(kp[kc * 8]);
                uint32_t b1 = f2tf32(kp[kc * 8 + 4]);
                MMA_TF32(sc[nt], qf[kc], b0, b1);
            }
        }

        float x[4][4];
        float rm0 = -1e30f, rm1 = -1e30f;
#pragma unroll
        for (int nt = 0; nt < 4; nt++) {
            int s_b = s_tile + nt * 8 + fc * 2;
            x[nt][0] = (s_b     >= w0lo && s_b     <= t_r0) ? sc[nt][0] * SOFTMAX_SCALE : -1e30f;
            x[nt][1] = (s_b + 1 >= w0lo && s_b + 1 <= t_r0) ? sc[nt][1] * SOFTMAX_SCALE : -1e30f;
            x[nt][2] = (s_b     >= w1lo && s_b     <= t_r1) ? sc[nt][2] * SOFTMAX_SCALE : -1e30f;
            x[nt][3] = (s_b + 1 >= w1lo && s_b + 1 <= t_r1) ? sc[nt][3] * SOFTMAX_SCALE : -1e30f;
            rm0 = fmaxf(rm0, fmaxf(x[nt][0], x[nt][1]));
            rm1 = fmaxf(rm1, fmaxf(x[nt][2], x[nt][3]));
        }
        rm0 = qmax2(rm0);
        rm1 = qmax2(rm1);
        const float mn0 = fmaxf(m0, rm0);
        const float mn1 = fmaxf(m1, rm1);
        const float corr0 = __expf(m0 - mn0);
        const float corr1 = __expf(m1 - mn1);

        __syncwarp();
        float rs0 = 0.f, rs1 = 0.f;
        float* Pp0 = Ps + (w * 16 + fr) * P_STRIDE + fc * 2;
        float* Pp1 = Pp0 + 8 * P_STRIDE;
#pragma unroll
        for (int nt = 0; nt < 4; nt++) {
            float p00 = (x[nt][0] > -1e29f) ? __expf(x[nt][0] - mn0) : 0.f;
            float p01 = (x[nt][1] > -1e29f) ? __expf(x[nt][1] - mn0) : 0.f;
            float p10 = (x[nt][2] > -1e29f) ? __expf(x[nt][2] - mn1) : 0.f;
            float p11 = (x[nt][3] > -1e29f) ? __expf(x[nt][3] - mn1) : 0.f;
            rs0 += p00 + p01;
            rs1 += p10 + p11;
            Pp0[nt * 8]     = __uint_as_float(f2tf32(p00));
            Pp0[nt * 8 + 1] = __uint_as_float(f2tf32(p01));
            Pp1[nt * 8]     = __uint_as_float(f2tf32(p10));
            Pp1[nt * 8 + 1] = __uint_as_float(f2tf32(p11));
        }
        l0 = l0 * corr0 + qsum2(rs0);
        l1 = l1 * corr1 + qsum2(rs1);
        m0 = mn0;
        m1 = mn1;

#pragma unroll
        for (int nt = 0; nt < 16; nt++) {
            oa[nt][0] *= corr0;
            oa[nt][1] *= corr0;
            oa[nt][2] *= corr1;
            oa[nt][3] *= corr1;
        }
        __syncwarp();

        uint32_t pa[4][4];
        const float* Pr = Ps + (w * 16 + fr) * P_STRIDE + fc;
#pragma unroll
        for (int kc = 0; kc < 4; kc++) {
            pa[kc][0] = __float_as_uint(Pr[kc * 8]);
            pa[kc][1] = __float_as_uint(Pr[8 * P_STRIDE + kc * 8]);
            pa[kc][2] = __float_as_uint(Pr[kc * 8 + 4]);
            pa[kc][3] = __float_as_uint(Pr[8 * P_STRIDE + kc * 8 + 4]);
        }

        const float* Vb = Vs + cur * KV_SZ;
#pragma unroll
        for (int nt = 0; nt < 16; nt++) {
            const float* vp = Vb + fc * KV_STRIDE + nt * 8 + fr;
#pragma unroll
            for (int kc = 0; kc < 4; kc++) {
                uint32_t b0 = f2tf32(vp[kc * 8 * KV_STRIDE]);
                uint32_t b1 = f2tf32(vp[(kc * 8 + 4) * KV_STRIDE]);
                MMA_TF32(oa[nt], pa[kc], b0, b1);
            }
        }
        __syncwarp();
    }

    const float inv0 = 1.0f / l0;
    const float inv1 = 1.0f / l1;
    float* o0 = out + (((size_t)b * Tt + t_r0) * Hh + h) * Kk;
    float* o1 = out + (((size_t)b * Tt + t_r1) * Hh + h) * Kk;
#pragma unroll
    for (int nt = 0; nt < 16; nt++) {
        int d = nt * 8 + fc * 2;
        *(float2*)(o0 + d) = make_float2(oa[nt][0] * inv0, oa[nt][1] * inv0);
        *(float2*)(o1 + d) = make_float2(oa[nt][2] * inv1, oa[nt][3] * inv1);
    }
}

// --------------------------- launch --------------------------------------
extern "C" void kernel_launch(void* const* d_in, const int* in_sizes, int n_in,
                              void* d_out, int out_size) {
    const float* hidden  = (const float*)d_in[0];
    const float* wq      = (const float*)d_in[1];
    const float* wk      = (const float*)d_in[2];
    const float* wv      = (const float*)d_in[3];
    const float* wo      = (const float*)d_in[4];
    const float* q_scale = (const float*)d_in[5];
    const float* k_scale = (const float*)d_in[6];
    const int*   seg     = (const int*)d_in[7];
    float* out = (float*)d_out;

    float *qb, *kb, *vb, *ab;
    int* posb;
    __half *h16, *wq16, *wk16, *wv16, *wo16, *a16;
    cudaGetSymbolAddress((void**)&qb, g_q);
    cudaGetSymbolAddress((void**)&kb, g_k);
    cudaGetSymbolAddress((void**)&vb, g_v);
    cudaGetSymbolAddress((void**)&ab, g_attn);
    cudaGetSymbolAddress((void**)&posb, g_pos);
    cudaGetSymbolAddress((void**)&h16, g_h16);
    cudaGetSymbolAddress((void**)&wq16, g_wq16);
    cudaGetSymbolAddress((void**)&wk16, g_wk16);
    cudaGetSymbolAddress((void**)&wv16, g_wv16);
    cudaGetSymbolAddress((void**)&wo16, g_wo16);
    cudaGetSymbolAddress((void**)&a16, g_a16);

    static bool attr_set = false;
    if (!attr_set) {
        cudaFuncSetAttribute(fa_kernel,
                             cudaFuncAttributeMaxDynamicSharedMemorySize,
                             FA_SMEM_BYTES);
        attr_set = true;
    }

    // 0) convert inputs to fp16
    {
        int nh = MTOT * Dd;
        f2h_kernel<<<nh / (256 * 8), 256>>>(hidden, h16, nh);
        int nq = Dd * Hh * Kk;
        f2h_kernel<<<nq / (256 * 8), 256>>>(wq, wq16, nq);
        int nk = Dd * Gg * Kk;
        f2h_kernel<<<nk / (256 * 8), 256>>>(wk, wk16, nk);
        f2h_kernel<<<nk / (256 * 8), 256>>>(wv, wv16, nk);
        int no = Hh * Kk * Dd;
        f2h_kernel<<<no / (256 * 8), 256>>>(wo, wo16, no);
    }

    // 1) QKV projections (fp16 tensor cores)
    {
        dim3 blk(256);
        dim3 grdQ((Hh * Kk) / 128, MTOT / 128);
        hgemm_kernel<<<grdQ, blk>>>(MTOT, Hh * Kk, Dd, h16, wq16, qb);
        dim3 grdK((Gg * Kk) / 128, MTOT / 128);
        hgemm_kernel<<<grdK, blk>>>(MTOT, Gg * Kk, Dd, h16, wk16, kb);
        hgemm_kernel<<<grdK, blk>>>(MTOT, Gg * Kk, Dd, h16, wv16, vb);
    }

    // 2) positions
    pos_kernel<<<(MTOT + 255) / 256, 256>>>(seg, posb);

    // 3) RMSNorm + RoPE (in place) on q and k
    rms_rope_kernel<<<MTOT * Hh, 128>>>(qb, q_scale, posb, Hh);
    rms_rope_kernel<<<MTOT * Gg, 128>>>(kb, k_scale, posb, Gg);

    // 4) flash attention
    {
        dim3 grd(Tt / 32, Gg, Bb);
        fa_kernel<<<grd, 256, FA_SMEM_BYTES>>>(qb, kb, vb, posb, ab);
    }

    // 5) output projection (fp16 tensor cores)
    {
        int na = MTOT * Hh * Kk;
        f2h_kernel<<<na / (256 * 8), 256>>>(ab, a16, na);
        dim3 blk(256);
        dim3 grd(Dd / 128, MTOT / 128);
        hgemm_kernel<<<grd, blk>>>(MTOT, Dd, Hh * Kk, a16, wo16, out);
    }
}

// round 9
// speedup vs baseline: 3.6884x; 1.1777x over previous
#include <cuda_runtime.h>
#include <cuda_fp16.h>
#include <math.h>
#include <stdint.h>

// Problem constants
#define Bb 4
#define Tt 2048
#define Dd 2048
#define Hh 16
#define Gg 4
#define Kk 128
#define Rr 4          // H / G
#define EPS 1e-6f
#define ROPE_BASE 10000.0f
#define SOFTMAX_SCALE 0.08838834764831845f  // K^-0.5

#define MTOT (Bb * Tt)          // 8192 rows

// --------------------------- scratch (device globals; no mallocs) ------------
__device__ float  g_q[(size_t)MTOT * Hh * Kk];     // 64 MB (pre-norm q, f32)
__device__ float  g_k[(size_t)MTOT * Gg * Kk];     // 16 MB (pre-norm k, f32)
__device__ int    g_pos[MTOT];
__device__ __half g_h16[(size_t)MTOT * Dd];        // 32 MB
__device__ __half g_wq16[(size_t)Dd * Hh * Kk];
__device__ __half g_wk16[(size_t)Dd * Gg * Kk];
__device__ __half g_wv16[(size_t)Dd * Gg * Kk];
__device__ __half g_wo16[(size_t)Hh * Kk * Dd];
__device__ __half g_q16[(size_t)MTOT * Hh * Kk];   // 32 MB (post norm+rope, *scale)
__device__ __half g_k16[(size_t)MTOT * Gg * Kk];   // 8 MB
__device__ __half g_v16[(size_t)MTOT * Gg * Kk];   // 8 MB (direct hgemm output)
__device__ __half g_a16[(size_t)MTOT * Hh * Kk];   // 32 MB (attn out, half)

#define MMA_F16(acc, af, b0v, b1v)                                             \
    asm volatile(                                                              \
        "mma.sync.aligned.m16n8k16.row.col.f32.f16.f16.f32 "                   \
        "{%0,%1,%2,%3}, {%4,%5,%6,%7}, {%8,%9}, {%0,%1,%2,%3};\n"              \
        : "+f"((acc)[0]), "+f"((acc)[1]), "+f"((acc)[2]), "+f"((acc)[3])       \
        : "r"((af)[0]), "r"((af)[1]), "r"((af)[2]), "r"((af)[3]),              \
          "r"(b0v), "r"(b1v))

__device__ __forceinline__ uint32_t h2u(__half2 h) { return *(uint32_t*)&h; }

// --------------------------- f32 -> f16 convert ------------------------------
__global__ __launch_bounds__(256)
void f2h_kernel(const float* __restrict__ src, __half* __restrict__ dst, int n) {
    int i = (blockIdx.x * blockDim.x + threadIdx.x) * 8;
    if (i >= n) return;
    float4 x = *(const float4*)(src + i);
    float4 y = *(const float4*)(src + i + 4);
    __half2 h0 = __floats2half2_rn(x.x, x.y);
    __half2 h1 = __floats2half2_rn(x.z, x.w);
    __half2 h2 = __floats2half2_rn(y.x, y.y);
    __half2 h3 = __floats2half2_rn(y.z, y.w);
    uint4 o;
    o.x = h2u(h0); o.y = h2u(h1); o.z = h2u(h2); o.w = h2u(h3);
    *(uint4*)(dst + i) = o;
}

// =============================================================================
// FP16 tensor-core GEMM:  C[M,N] = A[M,Kd](f16) @ B[Kd,N](f16), OutT f32/f16
// =============================================================================
#define HA_STR 40
#define HB_STR 136

template <typename OutT>
__global__ __launch_bounds__(256)
void hgemm_kernel(int M, int N, int Kd,
                  const __half* __restrict__ A,
                  const __half* __restrict__ B,
                  OutT* __restrict__ C) {
    __shared__ __half As[2][128][HA_STR];
    __shared__ __half Bs[2][32][HB_STR];

    const int tid  = threadIdx.x;
    const int lane = tid & 31;
    const int wid  = tid >> 5;
    const int warpM = wid & 1;
    const int warpN = wid >> 1;

    const __half* Ag = A + (size_t)blockIdx.y * 128 * Kd;
    const __half* Bg = B + (size_t)blockIdx.x * 128;

    float acc[4][4][4];
#pragma unroll
    for (int i = 0; i < 4; i++)
#pragma unroll
        for (int j = 0; j < 4; j++)
#pragma unroll
            for (int r = 0; r < 4; r++) acc[i][j][r] = 0.f;

    auto issue_loads = [&](int buf, int k0) {
#pragma unroll
        for (int i = 0; i < 2; i++) {
            int idx = tid + i * 256;
            int r = idx >> 2, c = (idx & 3) * 8;
            uint32_t dst = (uint32_t)__cvta_generic_to_shared(&As[buf][r][c]);
            const __half* src = Ag + (size_t)r * Kd + k0 + c;
            asm volatile("cp.async.cg.shared.global [%0], [%1], 16;\n"
                         :: "r"(dst), "l"(src));
        }
#pragma unroll
        for (int i = 0; i < 2; i++) {
            int idx = tid + i * 256;
            int r = idx >> 4, c = (idx & 15) * 8;
            uint32_t dst = (uint32_t)__cvta_generic_to_shared(&Bs[buf][r][c]);
            const __half* src = Bg + (size_t)(k0 + r) * N + c;
            asm volatile("cp.async.cg.shared.global [%0], [%1], 16;\n"
                         :: "r"(dst), "l"(src));
        }
        asm volatile("cp.async.commit_group;\n");
    };

    issue_loads(0, 0);
    const int KT = Kd >> 5;
    const int fr = lane >> 2;
    const int fc = lane & 3;
    const int grp = lane >> 3;
    const int gr8 = lane & 7;

    for (int kt = 0; kt < KT; kt++) {
        asm volatile("cp.async.wait_group 0;\n");
        __syncthreads();
        const int cur = kt & 1;
        if (kt + 1 < KT) issue_loads(cur ^ 1, (kt + 1) << 5);

#pragma unroll
        for (int kc = 0; kc < 2; kc++) {
            uint32_t af[4][4];
            uint32_t bf[4][2];
#pragma unroll
            for (int mt = 0; mt < 4; mt++) {
                int row = warpM * 64 + mt * 16 + (grp & 1) * 8 + gr8;
                int col = kc * 16 + (grp >> 1) * 8;
                uint32_t addr = (uint32_t)__cvta_generic_to_shared(&As[cur][row][col]);
                asm volatile("ldmatrix.sync.aligned.m8n8.x4.shared.b16 "
                             "{%0,%1,%2,%3}, [%4];\n"
                             : "=r"(af[mt][0]), "=r"(af[mt][1]),
                               "=r"(af[mt][2]), "=r"(af[mt][3])
                             : "r"(addr));
            }
#pragma unroll
            for (int np = 0; np < 2; np++) {
                int krow = kc * 16 + (grp & 1) * 8 + gr8;
                int ncol = warpN * 32 + np * 16 + (grp >> 1) * 8;
                uint32_t addr = (uint32_t)__cvta_generic_to_shared(&Bs[cur][krow][ncol]);
                asm volatile("ldmatrix.sync.aligned.m8n8.x4.trans.shared.b16 "
                             "{%0,%1,%2,%3}, [%4];\n"
                             : "=r"(bf[np * 2][0]), "=r"(bf[np * 2][1]),
                               "=r"(bf[np * 2 + 1][0]), "=r"(bf[np * 2 + 1][1])
                             : "r"(addr));
            }
#pragma unroll
            for (int mt = 0; mt < 4; mt++)
#pragma unroll
                for (int nt = 0; nt < 4; nt++)
                    MMA_F16(acc[mt][nt], af[mt], bf[nt][0], bf[nt][1]);
        }
        __syncthreads();
    }

    OutT* Cg = C + (size_t)blockIdx.y * 128 * N + (size_t)blockIdx.x * 128;
#pragma unroll
    for (int mt = 0; mt < 4; mt++) {
#pragma unroll
        for (int nt = 0; nt < 4; nt++) {
            int row = warpM * 64 + mt * 16 + fr;
            int col = warpN * 32 + nt * 8 + fc * 2;
            if constexpr (sizeof(OutT) == 4) {
                *(float2*)((float*)Cg + (size_t)row * N + col) =
                    make_float2(acc[mt][nt][0], acc[mt][nt][1]);
                *(float2*)((float*)Cg + (size_t)(row + 8) * N + col) =
                    make_float2(acc[mt][nt][2], acc[mt][nt][3]);
            } else {
                *(uint32_t*)((__half*)Cg + (size_t)row * N + col) =
                    h2u(__floats2half2_rn(acc[mt][nt][0], acc[mt][nt][1]));
                *(uint32_t*)((__half*)Cg + (size_t)(row + 8) * N + col) =
                    h2u(__floats2half2_rn(acc[mt][nt][2], acc[mt][nt][3]));
            }
        }
    }
}

// --------------------------- positions from sorted segment ids ---------------
__global__ void pos_kernel(const int* __restrict__ seg, int* __restrict__ pos) {
    int idx = blockIdx.x * blockDim.x + threadIdx.x;
    if (idx >= MTOT) return;
    int b = idx / Tt;
    int t = idx % Tt;
    const int* row = seg + (size_t)b * Tt;
    int s = row[t];
    int lo = 0, hi = t;
    while (lo < hi) {
        int mid = (lo + hi) >> 1;
        if (row[mid] < s) lo = mid + 1; else hi = mid;
    }
    pos[idx] = t - lo;
}

// ---------------- fused RMSNorm + RoPE, f32 in -> f16 out --------------------
__global__ __launch_bounds__(128)
void rms_rope_kernel(const float* __restrict__ x, const float* __restrict__ scale,
                     const int* __restrict__ pos, __half* __restrict__ outh,
                     int NH, float post_mul) {
    const int bt = blockIdx.x / NH;
    const int h  = blockIdx.x % NH;
    const float* p = x + ((size_t)bt * NH + h) * Kk;
    __half* po = outh + ((size_t)bt * NH + h) * Kk;

    const int i = threadIdx.x;
    float v = p[i];

    __shared__ float red[4];
    __shared__ float sx[Kk];
    float sq = v * v;
#pragma unroll
    for (int o = 16; o; o >>= 1) sq += __shfl_xor_sync(0xffffffffu, sq, o);
    if ((i & 31) == 0) red[i >> 5] = sq;
    __syncthreads();
    float var = (red[0] + red[1] + red[2] + red[3]) * (1.0f / Kk);
    float xn  = v * rsqrtf(var + EPS) * scale[i];
    sx[i] = xn;
    __syncthreads();

    if (i < Kk / 2) {
        float x1 = sx[i];
        float x2 = sx[i + Kk / 2];
        float pp = (float)pos[bt];
        float inv = expf(-logf(ROPE_BASE) * (2.0f * (float)i / (float)Kk));
        float ang = pp * inv;
        float s, c;
        sincosf(ang, &s, &c);
        po[i]           = __float2half_rn((x1 * c - x2 * s) * post_mul);
        po[i + Kk / 2]  = __float2half_rn((x2 * c + x1 * s) * post_mul);
    }
}

// =============================================================================
// Flash attention, fp16 tensor cores (m16n8k16), P kept in registers.
// Block = (32-query tile, g, b); 8 warps; warp w: head w>>1, 16 query rows.
// q is pre-scaled by SOFTMAX_SCALE. Key window [t-pos[t], t].
// =============================================================================
#define KV_STR 136

__device__ __forceinline__ float qmax2(float x) {
    x = fmaxf(x, __shfl_xor_sync(0xffffffffu, x, 1));
    x = fmaxf(x, __shfl_xor_sync(0xffffffffu, x, 2));
    return x;
}
__device__ __forceinline__ float qsum2(float x) {
    x += __shfl_xor_sync(0xffffffffu, x, 1);
    x += __shfl_xor_sync(0xffffffffu, x, 2);
    return x;
}

__global__ __launch_bounds__(256)
void fa16_kernel(const __half* __restrict__ q, const __half* __restrict__ k,
                 const __half* __restrict__ v, const int* __restrict__ pos,
                 __half* __restrict__ out) {
    __shared__ __half Ks[2][32][KV_STR];
    __shared__ __half Vs[2][32][KV_STR];

    const int tid  = threadIdx.x;
    const int lane = tid & 31;
    const int w    = tid >> 5;
    const int t0   = blockIdx.x * 32;
    const int g    = blockIdx.y;
    const int b    = blockIdx.z;

    const int h_local = w >> 1;
    const int q_base  = (w & 1) * 16;
    const int h = g * Rr + h_local;

    const int fr = lane >> 2;
    const int fc = lane & 3;

    const int t_r0 = t0 + q_base + fr;
    const int t_r1 = t_r0 + 8;
    const int w0lo = t_r0 - pos[b * Tt + t_r0];
    const int w1lo = t_r1 - pos[b * Tt + t_r1];

    // Q fragments: 8 chunks of k16
    uint32_t qf[8][4];
    {
        const __half* q0p = q + (((size_t)b * Tt + t_r0) * Hh + h) * Kk;
        const __half* q1p = q + (((size_t)b * Tt + t_r1) * Hh + h) * Kk;
#pragma unroll
        for (int kc = 0; kc < 8; kc++) {
            qf[kc][0] = *(const uint32_t*)(q0p + kc * 16 + 2 * fc);
            qf[kc][1] = *(const uint32_t*)(q1p + kc * 16 + 2 * fc);
            qf[kc][2] = *(const uint32_t*)(q0p + kc * 16 + 8 + 2 * fc);
            qf[kc][3] = *(const uint32_t*)(q1p + kc * 16 + 8 + 2 * fc);
        }
    }

    float oa[16][4];
#pragma unroll
    for (int i = 0; i < 16; i++)
#pragma unroll
        for (int j = 0; j < 4; j++) oa[i][j] = 0.f;
    float m0 = -1e30f, m1 = -1e30f, l0 = 0.f, l1 = 0.f;

    const int s_begin = (t0 - pos[b * Tt + t0]) & ~31;
    const int n_tiles = ((t0 + 31 - s_begin) >> 5) + 1;

    const __half* kg = k + ((size_t)b * Tt * Gg + g) * Kk;
    const __half* vg = v + ((size_t)b * Tt * Gg + g) * Kk;

    auto load_tile = [&](int buf, int s_tile) {
#pragma unroll
        for (int i = 0; i < 2; i++) {
            int idx = tid + i * 256;
            int r = idx >> 4, c = (idx & 15) * 8;
            uint32_t dst = (uint32_t)__cvta_generic_to_shared(&Ks[buf][r][c]);
            const __half* src = kg + (size_t)(s_tile + r) * Gg * Kk + c;
            asm volatile("cp.async.cg.shared.global [%0], [%1], 16;\n"
                         :: "r"(dst), "l"(src));
        }
#pragma unroll
        for (int i = 0; i < 2; i++) {
            int idx = tid + i * 256;
            int r = idx >> 4, c = (idx & 15) * 8;
            uint32_t dst = (uint32_t)__cvta_generic_to_shared(&Vs[buf][r][c]);
            const __half* src = vg + (size_t)(s_tile + r) * Gg * Kk + c;
            asm volatile("cp.async.cg.shared.global [%0], [%1], 16;\n"
                         :: "r"(dst), "l"(src));
        }
        asm volatile("cp.async.commit_group;\n");
    };

    load_tile(0, s_begin);

    for (int it = 0; it < n_tiles; it++) {
        const int s_tile = s_begin + it * 32;
        asm volatile("cp.async.wait_group 0;\n");
        __syncthreads();
        const int cur = it & 1;
        if (it + 1 < n_tiles) load_tile(cur ^ 1, s_tile + 32);

        // ---- scores: S[16,32] = Q @ K^T (q pre-scaled) ----
        float sc[4][4];
#pragma unroll
        for (int nt = 0; nt < 4; nt++)
#pragma unroll
            for (int i = 0; i < 4; i++) sc[nt][i] = 0.f;

#pragma unroll
        for (int nt = 0; nt < 4; nt++) {
#pragma unroll
            for (int kcp = 0; kcp < 4; kcp++) {
                uint32_t r0, r1, r2, r3;
                uint32_t addr = (uint32_t)__cvta_generic_to_shared(
                    &Ks[cur][nt * 8 + (lane & 7)][kcp * 32 + 8 * (lane >> 3)]);
                asm volatile("ldmatrix.sync.aligned.m8n8.x4.shared.b16 "
                             "{%0,%1,%2,%3}, [%4];\n"
                             : "=r"(r0), "=r"(r1), "=r"(r2), "=r"(r3)
                             : "r"(addr));
                MMA_F16(sc[nt], qf[2 * kcp], r0, r1);
                MMA_F16(sc[nt], qf[2 * kcp + 1], r2, r3);
            }
        }

        // ---- mask + online softmax ----
        float x[4][4];
        float rm0 = -1e30f, rm1 = -1e30f;
#pragma unroll
        for (int nt = 0; nt < 4; nt++) {
            int s_b = s_tile + nt * 8 + fc * 2;
            x[nt][0] = (s_b     >= w0lo && s_b     <= t_r0) ? sc[nt][0] : -1e30f;
            x[nt][1] = (s_b + 1 >= w0lo && s_b + 1 <= t_r0) ? sc[nt][1] : -1e30f;
            x[nt][2] = (s_b     >= w1lo && s_b     <= t_r1) ? sc[nt][2] : -1e30f;
            x[nt][3] = (s_b + 1 >= w1lo && s_b + 1 <= t_r1) ? sc[nt][3] : -1e30f;
            rm0 = fmaxf(rm0, fmaxf(x[nt][0], x[nt][1]));
            rm1 = fmaxf(rm1, fmaxf(x[nt][2], x[nt][3]));
        }
        rm0 = qmax2(rm0);
        rm1 = qmax2(rm1);
        const float mn0 = fmaxf(m0, rm0);
        const float mn1 = fmaxf(m1, rm1);
        const float corr0 = __expf(m0 - mn0);
        const float corr1 = __expf(m1 - mn1);

        float e[4][4];
        float rs0 = 0.f, rs1 = 0.f;
#pragma unroll
        for (int nt = 0; nt < 4; nt++) {
            e[nt][0] = (x[nt][0] > -1e29f) ? __expf(x[nt][0] - mn0) : 0.f;
            e[nt][1] = (x[nt][1] > -1e29f) ? __expf(x[nt][1] - mn0) : 0.f;
            e[nt][2] = (x[nt][2] > -1e29f) ? __expf(x[nt][2] - mn1) : 0.f;
            e[nt][3] = (x[nt][3] > -1e29f) ? __expf(x[nt][3] - mn1) : 0.f;
            rs0 += e[nt][0] + e[nt][1];
            rs1 += e[nt][2] + e[nt][3];
        }
        l0 = l0 * corr0 + qsum2(rs0);
        l1 = l1 * corr1 + qsum2(rs1);
        m0 = mn0;
        m1 = mn1;

        // ---- pack P into A fragments (registers only) ----
        uint32_t pa[2][4];
#pragma unroll
        for (int kc2 = 0; kc2 < 2; kc2++) {
            pa[kc2][0] = h2u(__floats2half2_rn(e[2 * kc2][0],     e[2 * kc2][1]));
            pa[kc2][1] = h2u(__floats2half2_rn(e[2 * kc2][2],     e[2 * kc2][3]));
            pa[kc2][2] = h2u(__floats2half2_rn(e[2 * kc2 + 1][0], e[2 * kc2 + 1][1]));
            pa[kc2][3] = h2u(__floats2half2_rn(e[2 * kc2 + 1][2], e[2 * kc2 + 1][3]));
        }

#pragma unroll
        for (int nt = 0; nt < 16; nt++) {
            oa[nt][0] *= corr0;
            oa[nt][1] *= corr0;
            oa[nt][2] *= corr1;
            oa[nt][3] *= corr1;
        }

        // ---- O += P @ V ----
#pragma unroll
        for (int nt2 = 0; nt2 < 8; nt2++) {
#pragma unroll
            for (int kc2 = 0; kc2 < 2; kc2++) {
                uint32_t r0, r1, r2, r3;
                uint32_t addr = (uint32_t)__cvta_generic_to_shared(
                    &Vs[cur][kc2 * 16 + 8 * ((lane >> 3) & 1) + (lane & 7)]
                       [nt2 * 16 + 8 * (lane >> 4)]);
                asm volatile("ldmatrix.sync.aligned.m8n8.x4.trans.shared.b16 "
                             "{%0,%1,%2,%3}, [%4];\n"
                             : "=r"(r0), "=r"(r1), "=r"(r2), "=r"(r3)
                             : "r"(addr));
                MMA_F16(oa[2 * nt2], pa[kc2], r0, r1);
                MMA_F16(oa[2 * nt2 + 1], pa[kc2], r2, r3);
            }
        }
        __syncthreads();
    }

    // ---- epilogue: write half ----
    const float inv0 = 1.0f / l0;
    const float inv1 = 1.0f / l1;
    __half* o0 = out + (((size_t)b * Tt + t_r0) * Hh + h) * Kk;
    __half* o1 = out + (((size_t)b * Tt + t_r1) * Hh + h) * Kk;
#pragma unroll
    for (int nt = 0; nt < 16; nt++) {
        int d = nt * 8 + fc * 2;
        *(uint32_t*)(o0 + d) = h2u(__floats2half2_rn(oa[nt][0] * inv0, oa[nt][1] * inv0));
        *(uint32_t*)(o1 + d) = h2u(__floats2half2_rn(oa[nt][2] * inv1, oa[nt][3] * inv1));
    }
}

// --------------------------- launch --------------------------------------
extern "C" void kernel_launch(void* const* d_in, const int* in_sizes, int n_in,
                              void* d_out, int out_size) {
    const float* hidden  = (const float*)d_in[0];
    const float* wq      = (const float*)d_in[1];
    const float* wk      = (const float*)d_in[2];
    const float* wv      = (const float*)d_in[3];
    const float* wo      = (const float*)d_in[4];
    const float* q_scale = (const float*)d_in[5];
    const float* k_scale = (const float*)d_in[6];
    const int*   seg     = (const int*)d_in[7];
    float* out = (float*)d_out;

    float *qb, *kb;
    int* posb;
    __half *h16, *wq16, *wk16, *wv16, *wo16, *q16, *k16, *v16, *a16;
    cudaGetSymbolAddress((void**)&qb, g_q);
    cudaGetSymbolAddress((void**)&kb, g_k);
    cudaGetSymbolAddress((void**)&posb, g_pos);
    cudaGetSymbolAddress((void**)&h16, g_h16);
    cudaGetSymbolAddress((void**)&wq16, g_wq16);
    cudaGetSymbolAddress((void**)&wk16, g_wk16);
    cudaGetSymbolAddress((void**)&wv16, g_wv16);
    cudaGetSymbolAddress((void**)&wo16, g_wo16);
    cudaGetSymbolAddress((void**)&q16, g_q16);
    cudaGetSymbolAddress((void**)&k16, g_k16);
    cudaGetSymbolAddress((void**)&v16, g_v16);
    cudaGetSymbolAddress((void**)&a16, g_a16);

    // 0) convert inputs to fp16
    {
        int nh = MTOT * Dd;
        f2h_kernel<<<nh / (256 * 8), 256>>>(hidden, h16, nh);
        int nq = Dd * Hh * Kk;
        f2h_kernel<<<nq / (256 * 8), 256>>>(wq, wq16, nq);
        int nk = Dd * Gg * Kk;
        f2h_kernel<<<nk / (256 * 8), 256>>>(wk, wk16, nk);
        f2h_kernel<<<nk / (256 * 8), 256>>>(wv, wv16, nk);
        int no = Hh * Kk * Dd;
        f2h_kernel<<<no / (256 * 8), 256>>>(wo, wo16, no);
    }

    // 1) QKV projections
    {
        dim3 blk(256);
        dim3 grdQ((Hh * Kk) / 128, MTOT / 128);
        hgemm_kernel<float><<<grdQ, blk>>>(MTOT, Hh * Kk, Dd, h16, wq16, qb);
        dim3 grdK((Gg * Kk) / 128, MTOT / 128);
        hgemm_kernel<float><<<grdK, blk>>>(MTOT, Gg * Kk, Dd, h16, wk16, kb);
        hgemm_kernel<__half><<<grdK, blk>>>(MTOT, Gg * Kk, Dd, h16, wv16, v16);
    }

    // 2) positions
    pos_kernel<<<(MTOT + 255) / 256, 256>>>(seg, posb);

    // 3) RMSNorm + RoPE -> fp16 (q pre-scaled by softmax scale)
    rms_rope_kernel<<<MTOT * Hh, 128>>>(qb, q_scale, posb, q16, Hh, SOFTMAX_SCALE);
    rms_rope_kernel<<<MTOT * Gg, 128>>>(kb, k_scale, posb, k16, Gg, 1.0f);

    // 4) flash attention (fp16)
    {
        dim3 grd(Tt / 32, Gg, Bb);
        fa16_kernel<<<grd, 256>>>(q16, k16, v16, posb, a16);
    }

    // 5) output projection (f32 out)
    {
        dim3 blk(256);
        dim3 grd(Dd / 128, MTOT / 128);
        hgemm_kernel<float><<<grd, blk>>>(MTOT, Dd, Hh * Kk, a16, wo16, out);
    }
}

// round 10
// speedup vs baseline: 3.6918x; 1.0009x over previous
#include <cuda_runtime.h>
#include <cuda_fp16.h>
#include <math.h>
#include <stdint.h>

// Problem constants
#define Bb 4
#define Tt 2048
#define Dd 2048
#define Hh 16
#define Gg 4
#define Kk 128
#define Rr 4          // H / G
#define EPS 1e-6f
#define ROPE_BASE 10000.0f
#define SOFTMAX_SCALE 0.08838834764831845f  // K^-0.5

#define MTOT (Bb * Tt)          // 8192 rows

// --------------------------- scratch (device globals; no mallocs) ------------
__device__ float  g_q[(size_t)MTOT * Hh * Kk];     // 64 MB (pre-norm q, f32)
__device__ float  g_k[(size_t)MTOT * Gg * Kk];     // 16 MB (pre-norm k, f32)
__device__ int    g_pos[MTOT];
__device__ __half g_h16[(size_t)MTOT * Dd];        // 32 MB
__device__ __half g_wq16[(size_t)Dd * Hh * Kk];
__device__ __half g_wk16[(size_t)Dd * Gg * Kk];
__device__ __half g_wv16[(size_t)Dd * Gg * Kk];
__device__ __half g_wo16[(size_t)Hh * Kk * Dd];
__device__ __half g_q16[(size_t)MTOT * Hh * Kk];   // 32 MB (post norm+rope, *scale)
__device__ __half g_k16[(size_t)MTOT * Gg * Kk];   // 8 MB
__device__ __half g_v16[(size_t)MTOT * Gg * Kk];   // 8 MB (direct hgemm output)
__device__ __half g_a16[(size_t)MTOT * Hh * Kk];   // 32 MB (attn out, half)

#define MMA_F16(acc, af, b0v, b1v)                                             \
    asm volatile(                                                              \
        "mma.sync.aligned.m16n8k16.row.col.f32.f16.f16.f32 "                   \
        "{%0,%1,%2,%3}, {%4,%5,%6,%7}, {%8,%9}, {%0,%1,%2,%3};\n"              \
        : "+f"((acc)[0]), "+f"((acc)[1]), "+f"((acc)[2]), "+f"((acc)[3])       \
        : "r"((af)[0]), "r"((af)[1]), "r"((af)[2]), "r"((af)[3]),              \
          "r"(b0v), "r"(b1v))

__device__ __forceinline__ uint32_t h2u(__half2 h) { return *(uint32_t*)&h; }

// --------------------------- f32 -> f16 convert ------------------------------
__global__ __launch_bounds__(256)
void f2h_kernel(const float* __restrict__ src, __half* __restrict__ dst, int n) {
    int i = (blockIdx.x * blockDim.x + threadIdx.x) * 8;
    if (i >= n) return;
    float4 x = *(const float4*)(src + i);
    float4 y = *(const float4*)(src + i + 4);
    __half2 h0 = __floats2half2_rn(x.x, x.y);
    __half2 h1 = __floats2half2_rn(x.z, x.w);
    __half2 h2 = __floats2half2_rn(y.x, y.y);
    __half2 h3 = __floats2half2_rn(y.z, y.w);
    uint4 o;
    o.x = h2u(h0); o.y = h2u(h1); o.z = h2u(h2); o.w = h2u(h3);
    *(uint4*)(dst + i) = o;
}

// =============================================================================
// FP16 tensor-core GEMM:  C[M,N] = A[M,Kd](f16) @ B[Kd,N](f16), OutT f32/f16
// =============================================================================
#define HA_STR 40
#define HB_STR 136

template <typename OutT>
__global__ __launch_bounds__(256)
void hgemm_kernel(int M, int N, int Kd,
                  const __half* __restrict__ A,
                  const __half* __restrict__ B,
                  OutT* __restrict__ C) {
    __shared__ __half As[2][128][HA_STR];
    __shared__ __half Bs[2][32][HB_STR];

    const int tid  = threadIdx.x;
    const int lane = tid & 31;
    const int wid  = tid >> 5;
    const int warpM = wid & 1;
    const int warpN = wid >> 1;

    const __half* Ag = A + (size_t)blockIdx.y * 128 * Kd;
    const __half* Bg = B + (size_t)blockIdx.x * 128;

    float acc[4][4][4];
#pragma unroll
    for (int i = 0; i < 4; i++)
#pragma unroll
        for (int j = 0; j < 4; j++)
#pragma unroll
            for (int r = 0; r < 4; r++) acc[i][j][r] = 0.f;

    auto issue_loads = [&](int buf, int k0) {
#pragma unroll
        for (int i = 0; i < 2; i++) {
            int idx = tid + i * 256;
            int r = idx >> 2, c = (idx & 3) * 8;
            uint32_t dst = (uint32_t)__cvta_generic_to_shared(&As[buf][r][c]);
            const __half* src = Ag + (size_t)r * Kd + k0 + c;
            asm volatile("cp.async.cg.shared.global [%0], [%1], 16;\n"
                         :: "r"(dst), "l"(src));
        }
#pragma unroll
        for (int i = 0; i < 2; i++) {
            int idx = tid + i * 256;
            int r = idx >> 4, c = (idx & 15) * 8;
            uint32_t dst = (uint32_t)__cvta_generic_to_shared(&Bs[buf][r][c]);
            const __half* src = Bg + (size_t)(k0 + r) * N + c;
            asm volatile("cp.async.cg.shared.global [%0], [%1], 16;\n"
                         :: "r"(dst), "l"(src));
        }
        asm volatile("cp.async.commit_group;\n");
    };

    issue_loads(0, 0);
    const int KT = Kd >> 5;
    const int fr = lane >> 2;
    const int fc = lane & 3;
    const int grp = lane >> 3;
    const int gr8 = lane & 7;

    for (int kt = 0; kt < KT; kt++) {
        asm volatile("cp.async.wait_group 0;\n");
        __syncthreads();
        const int cur = kt & 1;
        if (kt + 1 < KT) issue_loads(cur ^ 1, (kt + 1) << 5);

#pragma unroll
        for (int kc = 0; kc < 2; kc++) {
            uint32_t af[4][4];
            uint32_t bf[4][2];
#pragma unroll
            for (int mt = 0; mt < 4; mt++) {
                int row = warpM * 64 + mt * 16 + (grp & 1) * 8 + gr8;
                int col = kc * 16 + (grp >> 1) * 8;
                uint32_t addr = (uint32_t)__cvta_generic_to_shared(&As[cur][row][col]);
                asm volatile("ldmatrix.sync.aligned.m8n8.x4.shared.b16 "
                             "{%0,%1,%2,%3}, [%4];\n"
                             : "=r"(af[mt][0]), "=r"(af[mt][1]),
                               "=r"(af[mt][2]), "=r"(af[mt][3])
                             : "r"(addr));
            }
#pragma unroll
            for (int np = 0; np < 2; np++) {
                int krow = kc * 16 + (grp & 1) * 8 + gr8;
                int ncol = warpN * 32 + np * 16 + (grp >> 1) * 8;
                uint32_t addr = (uint32_t)__cvta_generic_to_shared(&Bs[cur][krow][ncol]);
                asm volatile("ldmatrix.sync.aligned.m8n8.x4.trans.shared.b16 "
                             "{%0,%1,%2,%3}, [%4];\n"
                             : "=r"(bf[np * 2][0]), "=r"(bf[np * 2][1]),
                               "=r"(bf[np * 2 + 1][0]), "=r"(bf[np * 2 + 1][1])
                             : "r"(addr));
            }
#pragma unroll
            for (int mt = 0; mt < 4; mt++)
#pragma unroll
                for (int nt = 0; nt < 4; nt++)
                    MMA_F16(acc[mt][nt], af[mt], bf[nt][0], bf[nt][1]);
        }
        __syncthreads();
    }

    OutT* Cg = C + (size_t)blockIdx.y * 128 * N + (size_t)blockIdx.x * 128;
#pragma unroll
    for (int mt = 0; mt < 4; mt++) {
#pragma unroll
        for (int nt = 0; nt < 4; nt++) {
            int row = warpM * 64 + mt * 16 + fr;
            int col = warpN * 32 + nt * 8 + fc * 2;
            if constexpr (sizeof(OutT) == 4) {
                *(float2*)((float*)Cg + (size_t)row * N + col) =
                    make_float2(acc[mt][nt][0], acc[mt][nt][1]);
                *(float2*)((float*)Cg + (size_t)(row + 8) * N + col) =
                    make_float2(acc[mt][nt][2], acc[mt][nt][3]);
            } else {
                *(uint32_t*)((__half*)Cg + (size_t)row * N + col) =
                    h2u(__floats2half2_rn(acc[mt][nt][0], acc[mt][nt][1]));
                *(uint32_t*)((__half*)Cg + (size_t)(row + 8) * N + col) =
                    h2u(__floats2half2_rn(acc[mt][nt][2], acc[mt][nt][3]));
            }
        }
    }
}

// --------------------------- positions from sorted segment ids ---------------
__global__ void pos_kernel(const int* __restrict__ seg, int* __restrict__ pos) {
    int idx = blockIdx.x * blockDim.x + threadIdx.x;
    if (idx >= MTOT) return;
    int b = idx / Tt;
    int t = idx % Tt;
    const int* row = seg + (size_t)b * Tt;
    int s = row[t];
    int lo = 0, hi = t;
    while (lo < hi) {
        int mid = (lo + hi) >> 1;
        if (row[mid] < s) lo = mid + 1; else hi = mid;
    }
    pos[idx] = t - lo;
}

// ---------------- fused RMSNorm + RoPE, f32 in -> f16 out --------------------
__global__ __launch_bounds__(128)
void rms_rope_kernel(const float* __restrict__ x, const float* __restrict__ scale,
                     const int* __restrict__ pos, __half* __restrict__ outh,
                     int NH, float post_mul) {
    const int bt = blockIdx.x / NH;
    const int h  = blockIdx.x % NH;
    const float* p = x + ((size_t)bt * NH + h) * Kk;
    __half* po = outh + ((size_t)bt * NH + h) * Kk;

    const int i = threadIdx.x;
    float v = p[i];

    __shared__ float red[4];
    __shared__ float sx[Kk];
    float sq = v * v;
#pragma unroll
    for (int o = 16; o; o >>= 1) sq += __shfl_xor_sync(0xffffffffu, sq, o);
    if ((i & 31) == 0) red[i >> 5] = sq;
    __syncthreads();
    float var = (red[0] + red[1] + red[2] + red[3]) * (1.0f / Kk);
    float xn  = v * rsqrtf(var + EPS) * scale[i];
    sx[i] = xn;
    __syncthreads();

    if (i < Kk / 2) {
        float x1 = sx[i];
        float x2 = sx[i + Kk / 2];
        float pp = (float)pos[bt];
        float inv = expf(-logf(ROPE_BASE) * (2.0f * (float)i / (float)Kk));
        float ang = pp * inv;
        float s, c;
        sincosf(ang, &s, &c);
        po[i]           = __float2half_rn((x1 * c - x2 * s) * post_mul);
        po[i + Kk / 2]  = __float2half_rn((x2 * c + x1 * s) * post_mul);
    }
}

// =============================================================================
// Flash attention, fp16 tensor cores (m16n8k16), P kept in registers.
// Block = (32-query tile, g, b); 8 warps; warp w: head w>>1, 16 query rows.
// q is pre-scaled by SOFTMAX_SCALE. Key window [t-pos[t], t].
// =============================================================================
#define KV_STR 136

__device__ __forceinline__ float qmax2(float x) {
    x = fmaxf(x, __shfl_xor_sync(0xffffffffu, x, 1));
    x = fmaxf(x, __shfl_xor_sync(0xffffffffu, x, 2));
    return x;
}
__device__ __forceinline__ float qsum2(float x) {
    x += __shfl_xor_sync(0xffffffffu, x, 1);
    x += __shfl_xor_sync(0xffffffffu, x, 2);
    return x;
}

__global__ __launch_bounds__(256)
void fa16_kernel(const __half* __restrict__ q, const __half* __restrict__ k,
                 const __half* __restrict__ v, const int* __restrict__ pos,
                 __half* __restrict__ out) {
    __shared__ __half Ks[2][32][KV_STR];
    __shared__ __half Vs[2][32][KV_STR];

    const int tid  = threadIdx.x;
    const int lane = tid & 31;
    const int w    = tid >> 5;
    const int t0   = blockIdx.x * 32;
    const int g    = blockIdx.y;
    const int b    = blockIdx.z;

    const int h_local = w >> 1;
    const int q_base  = (w & 1) * 16;
    const int h = g * Rr + h_local;

    const int fr = lane >> 2;
    const int fc = lane & 3;

    const int t_r0 = t0 + q_base + fr;
    const int t_r1 = t_r0 + 8;
    const int w0lo = t_r0 - pos[b * Tt + t_r0];
    const int w1lo = t_r1 - pos[b * Tt + t_r1];

    // Q fragments: 8 chunks of k16
    uint32_t qf[8][4];
    {
        const __half* q0p = q + (((size_t)b * Tt + t_r0) * Hh + h) * Kk;
        const __half* q1p = q + (((size_t)b * Tt + t_r1) * Hh + h) * Kk;
#pragma unroll
        for (int kc = 0; kc < 8; kc++) {
            qf[kc][0] = *(const uint32_t*)(q0p + kc * 16 + 2 * fc);
            qf[kc][1] = *(const uint32_t*)(q1p + kc * 16 + 2 * fc);
            qf[kc][2] = *(const uint32_t*)(q0p + kc * 16 + 8 + 2 * fc);
            qf[kc][3] = *(const uint32_t*)(q1p + kc * 16 + 8 + 2 * fc);
        }
    }

    float oa[16][4];
#pragma unroll
    for (int i = 0; i < 16; i++)
#pragma unroll
        for (int j = 0; j < 4; j++) oa[i][j] = 0.f;
    float m0 = -1e30f, m1 = -1e30f, l0 = 0.f, l1 = 0.f;

    const int s_begin = (t0 - pos[b * Tt + t0]) & ~31;
    const int n_tiles = ((t0 + 31 - s_begin) >> 5) + 1;

    const __half* kg = k + ((size_t)b * Tt * Gg + g) * Kk;
    const __half* vg = v + ((size_t)b * Tt * Gg + g) * Kk;

    auto load_tile = [&](int buf, int s_tile) {
#pragma unroll
        for (int i = 0; i < 2; i++) {
            int idx = tid + i * 256;
            int r = idx >> 4, c = (idx & 15) * 8;
            uint32_t dst = (uint32_t)__cvta_generic_to_shared(&Ks[buf][r][c]);
            const __half* src = kg + (size_t)(s_tile + r) * Gg * Kk + c;
            asm volatile("cp.async.cg.shared.global [%0], [%1], 16;\n"
                         :: "r"(dst), "l"(src));
        }
#pragma unroll
        for (int i = 0; i < 2; i++) {
            int idx = tid + i * 256;
            int r = idx >> 4, c = (idx & 15) * 8;
            uint32_t dst = (uint32_t)__cvta_generic_to_shared(&Vs[buf][r][c]);
            const __half* src = vg + (size_t)(s_tile + r) * Gg * Kk + c;
            asm volatile("cp.async.cg.shared.global [%0], [%1], 16;\n"
                         :: "r"(dst), "l"(src));
        }
        asm volatile("cp.async.commit_group;\n");
    };

    load_tile(0, s_begin);

    for (int it = 0; it < n_tiles; it++) {
        const int s_tile = s_begin + it * 32;
        asm volatile("cp.async.wait_group 0;\n");
        __syncthreads();
        const int cur = it & 1;
        if (it + 1 < n_tiles) load_tile(cur ^ 1, s_tile + 32);

        // ---- scores: S[16,32] = Q @ K^T (q pre-scaled) ----
        float sc[4][4];
#pragma unroll
        for (int nt = 0; nt < 4; nt++)
#pragma unroll
            for (int i = 0; i < 4; i++) sc[nt][i] = 0.f;

#pragma unroll
        for (int nt = 0; nt < 4; nt++) {
#pragma unroll
            for (int kcp = 0; kcp < 4; kcp++) {
                uint32_t r0, r1, r2, r3;
                uint32_t addr = (uint32_t)__cvta_generic_to_shared(
                    &Ks[cur][nt * 8 + (lane & 7)][kcp * 32 + 8 * (lane >> 3)]);
                asm volatile("ldmatrix.sync.aligned.m8n8.x4.shared.b16 "
                             "{%0,%1,%2,%3}, [%4];\n"
                             : "=r"(r0), "=r"(r1), "=r"(r2), "=r"(r3)
                             : "r"(addr));
                MMA_F16(sc[nt], qf[2 * kcp], r0, r1);
                MMA_F16(sc[nt], qf[2 * kcp + 1], r2, r3);
            }
        }

        // ---- mask + online softmax ----
        float x[4][4];
        float rm0 = -1e30f, rm1 = -1e30f;
#pragma unroll
        for (int nt = 0; nt < 4; nt++) {
            int s_b = s_tile + nt * 8 + fc * 2;
            x[nt][0] = (s_b     >= w0lo && s_b     <= t_r0) ? sc[nt][0] : -1e30f;
            x[nt][1] = (s_b + 1 >= w0lo && s_b + 1 <= t_r0) ? sc[nt][1] : -1e30f;
            x[nt][2] = (s_b     >= w1lo && s_b     <= t_r1) ? sc[nt][2] : -1e30f;
            x[nt][3] = (s_b + 1 >= w1lo && s_b + 1 <= t_r1) ? sc[nt][3] : -1e30f;
            rm0 = fmaxf(rm0, fmaxf(x[nt][0], x[nt][1]));
            rm1 = fmaxf(rm1, fmaxf(x[nt][2], x[nt][3]));
        }
        rm0 = qmax2(rm0);
        rm1 = qmax2(rm1);
        const float mn0 = fmaxf(m0, rm0);
        const float mn1 = fmaxf(m1, rm1);
        const float corr0 = __expf(m0 - mn0);
        const float corr1 = __expf(m1 - mn1);

        float e[4][4];
        float rs0 = 0.f, rs1 = 0.f;
#pragma unroll
        for (int nt = 0; nt < 4; nt++) {
            e[nt][0] = (x[nt][0] > -1e29f) ? __expf(x[nt][0] - mn0) : 0.f;
            e[nt][1] = (x[nt][1] > -1e29f) ? __expf(x[nt][1] - mn0) : 0.f;
            e[nt][2] = (x[nt][2] > -1e29f) ? __expf(x[nt][2] - mn1) : 0.f;
            e[nt][3] = (x[nt][3] > -1e29f) ? __expf(x[nt][3] - mn1) : 0.f;
            rs0 += e[nt][0] + e[nt][1];
            rs1 += e[nt][2] + e[nt][3];
        }
        l0 = l0 * corr0 + qsum2(rs0);
        l1 = l1 * corr1 + qsum2(rs1);
        m0 = mn0;
        m1 = mn1;

        // ---- pack P into A fragments (registers only) ----
        uint32_t pa[2][4];
#pragma unroll
        for (int kc2 = 0; kc2 < 2; kc2++) {
            pa[kc2][0] = h2u(__floats2half2_rn(e[2 * kc2][0],     e[2 * kc2][1]));
            pa[kc2][1] = h2u(__floats2half2_rn(e[2 * kc2][2],     e[2 * kc2][3]));
            pa[kc2][2] = h2u(__floats2half2_rn(e[2 * kc2 + 1][0], e[2 * kc2 + 1][1]));
            pa[kc2][3] = h2u(__floats2half2_rn(e[2 * kc2 + 1][2], e[2 * kc2 + 1][3]));
        }

#pragma unroll
        for (int nt = 0; nt < 16; nt++) {
            oa[nt][0] *= corr0;
            oa[nt][1] *= corr0;
            oa[nt][2] *= corr1;
            oa[nt][3] *= corr1;
        }

        // ---- O += P @ V ----
#pragma unroll
        for (int nt2 = 0; nt2 < 8; nt2++) {
#pragma unroll
            for (int kc2 = 0; kc2 < 2; kc2++) {
                uint32_t r0, r1, r2, r3;
                uint32_t addr = (uint32_t)__cvta_generic_to_shared(
                    &Vs[cur][kc2 * 16 + 8 * ((lane >> 3) & 1) + (lane & 7)]
                       [nt2 * 16 + 8 * (lane >> 4)]);
                asm volatile("ldmatrix.sync.aligned.m8n8.x4.trans.shared.b16 "
                             "{%0,%1,%2,%3}, [%4];\n"
                             : "=r"(r0), "=r"(r1), "=r"(r2), "=r"(r3)
                             : "r"(addr));
                MMA_F16(oa[2 * nt2], pa[kc2], r0, r1);
                MMA_F16(oa[2 * nt2 + 1], pa[kc2], r2, r3);
            }
        }
        __syncthreads();
    }

    // ---- epilogue: write half ----
    const float inv0 = 1.0f / l0;
    const float inv1 = 1.0f / l1;
    __half* o0 = out + (((size_t)b * Tt + t_r0) * Hh + h) * Kk;
    __half* o1 = out + (((size_t)b * Tt + t_r1) * Hh + h) * Kk;
#pragma unroll
    for (int nt = 0; nt < 16; nt++) {
        int d = nt * 8 + fc * 2;
        *(uint32_t*)(o0 + d) = h2u(__floats2half2_rn(oa[nt][0] * inv0, oa[nt][1] * inv0));
        *(uint32_t*)(o1 + d) = h2u(__floats2half2_rn(oa[nt][2] * inv1, oa[nt][3] * inv1));
    }
}

// --------------------------- launch --------------------------------------
extern "C" void kernel_launch(void* const* d_in, const int* in_sizes, int n_in,
                              void* d_out, int out_size) {
    const float* hidden  = (const float*)d_in[0];
    const float* wq      = (const float*)d_in[1];
    const float* wk      = (const float*)d_in[2];
    const float* wv      = (const float*)d_in[3];
    const float* wo      = (const float*)d_in[4];
    const float* q_scale = (const float*)d_in[5];
    const float* k_scale = (const float*)d_in[6];
    const int*   seg     = (const int*)d_in[7];
    float* out = (float*)d_out;

    float *qb, *kb;
    int* posb;
    __half *h16, *wq16, *wk16, *wv16, *wo16, *q16, *k16, *v16, *a16;
    cudaGetSymbolAddress((void**)&qb, g_q);
    cudaGetSymbolAddress((void**)&kb, g_k);
    cudaGetSymbolAddress((void**)&posb, g_pos);
    cudaGetSymbolAddress((void**)&h16, g_h16);
    cudaGetSymbolAddress((void**)&wq16, g_wq16);
    cudaGetSymbolAddress((void**)&wk16, g_wk16);
    cudaGetSymbolAddress((void**)&wv16, g_wv16);
    cudaGetSymbolAddress((void**)&wo16, g_wo16);
    cudaGetSymbolAddress((void**)&q16, g_q16);
    cudaGetSymbolAddress((void**)&k16, g_k16);
    cudaGetSymbolAddress((void**)&v16, g_v16);
    cudaGetSymbolAddress((void**)&a16, g_a16);

    // 0) convert inputs to fp16
    {
        int nh = MTOT * Dd;
        f2h_kernel<<<nh / (256 * 8), 256>>>(hidden, h16, nh);
        int nq = Dd * Hh * Kk;
        f2h_kernel<<<nq / (256 * 8), 256>>>(wq, wq16, nq);
        int nk = Dd * Gg * Kk;
        f2h_kernel<<<nk / (256 * 8), 256>>>(wk, wk16, nk);
        f2h_kernel<<<nk / (256 * 8), 256>>>(wv, wv16, nk);
        int no = Hh * Kk * Dd;
        f2h_kernel<<<no / (256 * 8), 256>>>(wo, wo16, no);
    }

    // 1) QKV projections
    {
        dim3 blk(256);
        dim3 grdQ((Hh * Kk) / 128, MTOT / 128);
        hgemm_kernel<float><<<grdQ, blk>>>(MTOT, Hh * Kk, Dd, h16, wq16, qb);
        dim3 grdK((Gg * Kk) / 128, MTOT / 128);
        hgemm_kernel<float><<<grdK, blk>>>(MTOT, Gg * Kk, Dd, h16, wk16, kb);
        hgemm_kernel<__half><<<grdK, blk>>>(MTOT, Gg * Kk, Dd, h16, wv16, v16);
    }

    // 2) positions
    pos_kernel<<<(MTOT + 255) / 256, 256>>>(seg, posb);

    // 3) RMSNorm + RoPE -> fp16 (q pre-scaled by softmax scale)
    rms_rope_kernel<<<MTOT * Hh, 128>>>(qb, q_scale, posb, q16, Hh, SOFTMAX_SCALE);
    rms_rope_kernel<<<MTOT * Gg, 128>>>(kb, k_scale, posb, k16, Gg, 1.0f);

    // 4) flash attention (fp16)
    {
        dim3 grd(Tt / 32, Gg, Bb);
        fa16_kernel<<<grd, 256>>>(q16, k16, v16, posb, a16);
    }

    // 5) output projection (f32 out)
    {
        dim3 blk(256);
        dim3 grd(Dd / 128, MTOT / 128);
        hgemm_kernel<float><<<grd, blk>>>(MTOT, Dd, Hh * Kk, a16, wo16, out);
    }
}

// round 11
// speedup vs baseline: 3.6979x; 1.0016x over previous
#include <cuda_runtime.h>
#include <cuda_fp16.h>
#include <math.h>
#include <stdint.h>

// Problem constants
#define Bb 4
#define Tt 2048
#define Dd 2048
#define Hh 16
#define Gg 4
#define Kk 128
#define Rr 4          // H / G
#define EPS 1e-6f
#define ROPE_BASE 10000.0f
#define SOFTMAX_SCALE 0.08838834764831845f  // K^-0.5

#define MTOT (Bb * Tt)          // 8192 rows

// --------------------------- scratch (device globals; no mallocs) ------------
__device__ float  g_q[(size_t)MTOT * Hh * Kk];     // 64 MB (pre-norm q, f32)
__device__ float  g_k[(size_t)MTOT * Gg * Kk];     // 16 MB (pre-norm k, f32)
__device__ int    g_pos[MTOT];
__device__ __half g_h16[(size_t)MTOT * Dd];        // 32 MB
__device__ __half g_wq16[(size_t)Dd * Hh * Kk];
__device__ __half g_wk16[(size_t)Dd * Gg * Kk];
__device__ __half g_wv16[(size_t)Dd * Gg * Kk];
__device__ __half g_wo16[(size_t)Hh * Kk * Dd];
__device__ __half g_q16[(size_t)MTOT * Hh * Kk];   // 32 MB (post norm+rope, *scale)
__device__ __half g_k16[(size_t)MTOT * Gg * Kk];   // 8 MB
__device__ __half g_v16[(size_t)MTOT * Gg * Kk];   // 8 MB (direct hgemm output)
__device__ __half g_a16[(size_t)MTOT * Hh * Kk];   // 32 MB (attn out, half)

#define MMA_F16(acc, af, b0v, b1v)                                             \
    asm volatile(                                                              \
        "mma.sync.aligned.m16n8k16.row.col.f32.f16.f16.f32 "                   \
        "{%0,%1,%2,%3}, {%4,%5,%6,%7}, {%8,%9}, {%0,%1,%2,%3};\n"              \
        : "+f"((acc)[0]), "+f"((acc)[1]), "+f"((acc)[2]), "+f"((acc)[3])       \
        : "r"((af)[0]), "r"((af)[1]), "r"((af)[2]), "r"((af)[3]),              \
          "r"(b0v), "r"(b1v))

__device__ __forceinline__ uint32_t h2u(__half2 h) { return *(uint32_t*)&h; }

// --------------------------- f32 -> f16 convert ------------------------------
__global__ __launch_bounds__(256)
void f2h_kernel(const float* __restrict__ src, __half* __restrict__ dst, int n) {
    int i = (blockIdx.x * blockDim.x + threadIdx.x) * 8;
    if (i >= n) return;
    float4 x = *(const float4*)(src + i);
    float4 y = *(const float4*)(src + i + 4);
    __half2 h0 = __floats2half2_rn(x.x, x.y);
    __half2 h1 = __floats2half2_rn(x.z, x.w);
    __half2 h2 = __floats2half2_rn(y.x, y.y);
    __half2 h3 = __floats2half2_rn(y.z, y.w);
    uint4 o;
    o.x = h2u(h0); o.y = h2u(h1); o.z = h2u(h2); o.w = h2u(h3);
    *(uint4*)(dst + i) = o;
}

// =============================================================================
// FP16 tensor-core GEMM:  C[M,N] = A[M,Kd](f16) @ B[Kd,N](f16), OutT f32/f16
// =============================================================================
#define HA_STR 40
#define HB_STR 136

template <typename OutT>
__global__ __launch_bounds__(256)
void hgemm_kernel(int M, int N, int Kd,
                  const __half* __restrict__ A,
                  const __half* __restrict__ B,
                  OutT* __restrict__ C) {
    __shared__ __half As[2][128][HA_STR];
    __shared__ __half Bs[2][32][HB_STR];

    const int tid  = threadIdx.x;
    const int lane = tid & 31;
    const int wid  = tid >> 5;
    const int warpM = wid & 1;
    const int warpN = wid >> 1;

    const __half* Ag = A + (size_t)blockIdx.y * 128 * Kd;
    const __half* Bg = B + (size_t)blockIdx.x * 128;

    float acc[4][4][4];
#pragma unroll
    for (int i = 0; i < 4; i++)
#pragma unroll
        for (int j = 0; j < 4; j++)
#pragma unroll
            for (int r = 0; r < 4; r++) acc[i][j][r] = 0.f;

    auto issue_loads = [&](int buf, int k0) {
#pragma unroll
        for (int i = 0; i < 2; i++) {
            int idx = tid + i * 256;
            int r = idx >> 2, c = (idx & 3) * 8;
            uint32_t dst = (uint32_t)__cvta_generic_to_shared(&As[buf][r][c]);
            const __half* src = Ag + (size_t)r * Kd + k0 + c;
            asm volatile("cp.async.cg.shared.global [%0], [%1], 16;\n"
                         :: "r"(dst), "l"(src));
        }
#pragma unroll
        for (int i = 0; i < 2; i++) {
            int idx = tid + i * 256;
            int r = idx >> 4, c = (idx & 15) * 8;
            uint32_t dst = (uint32_t)__cvta_generic_to_shared(&Bs[buf][r][c]);
            const __half* src = Bg + (size_t)(k0 + r) * N + c;
            asm volatile("cp.async.cg.shared.global [%0], [%1], 16;\n"
                         :: "r"(dst), "l"(src));
        }
        asm volatile("cp.async.commit_group;\n");
    };

    issue_loads(0, 0);
    const int KT = Kd >> 5;
    const int fr = lane >> 2;
    const int fc = lane & 3;
    const int grp = lane >> 3;
    const int gr8 = lane & 7;

    for (int kt = 0; kt < KT; kt++) {
        asm volatile("cp.async.wait_group 0;\n");
        __syncthreads();
        const int cur = kt & 1;
        if (kt + 1 < KT) issue_loads(cur ^ 1, (kt + 1) << 5);

#pragma unroll
        for (int kc = 0; kc < 2; kc++) {
            uint32_t af[4][4];
            uint32_t bf[4][2];
#pragma unroll
            for (int mt = 0; mt < 4; mt++) {
                int row = warpM * 64 + mt * 16 + (grp & 1) * 8 + gr8;
                int col = kc * 16 + (grp >> 1) * 8;
                uint32_t addr = (uint32_t)__cvta_generic_to_shared(&As[cur][row][col]);
                asm volatile("ldmatrix.sync.aligned.m8n8.x4.shared.b16 "
                             "{%0,%1,%2,%3}, [%4];\n"
                             : "=r"(af[mt][0]), "=r"(af[mt][1]),
                               "=r"(af[mt][2]), "=r"(af[mt][3])
                             : "r"(addr));
            }
#pragma unroll
            for (int np = 0; np < 2; np++) {
                int krow = kc * 16 + (grp & 1) * 8 + gr8;
                int ncol = warpN * 32 + np * 16 + (grp >> 1) * 8;
                uint32_t addr = (uint32_t)__cvta_generic_to_shared(&Bs[cur][krow][ncol]);
                asm volatile("ldmatrix.sync.aligned.m8n8.x4.trans.shared.b16 "
                             "{%0,%1,%2,%3}, [%4];\n"
                             : "=r"(bf[np * 2][0]), "=r"(bf[np * 2][1]),
                               "=r"(bf[np * 2 + 1][0]), "=r"(bf[np * 2 + 1][1])
                             : "r"(addr));
            }
#pragma unroll
            for (int mt = 0; mt < 4; mt++)
#pragma unroll
                for (int nt = 0; nt < 4; nt++)
                    MMA_F16(acc[mt][nt], af[mt], bf[nt][0], bf[nt][1]);
        }
        __syncthreads();
    }

    OutT* Cg = C + (size_t)blockIdx.y * 128 * N + (size_t)blockIdx.x * 128;
#pragma unroll
    for (int mt = 0; mt < 4; mt++) {
#pragma unroll
        for (int nt = 0; nt < 4; nt++) {
            int row = warpM * 64 + mt * 16 + fr;
            int col = warpN * 32 + nt * 8 + fc * 2;
            if constexpr (sizeof(OutT) == 4) {
                *(float2*)((float*)Cg + (size_t)row * N + col) =
                    make_float2(acc[mt][nt][0], acc[mt][nt][1]);
                *(float2*)((float*)Cg + (size_t)(row + 8) * N + col) =
                    make_float2(acc[mt][nt][2], acc[mt][nt][3]);
            } else {
                *(uint32_t*)((__half*)Cg + (size_t)row * N + col) =
                    h2u(__floats2half2_rn(acc[mt][nt][0], acc[mt][nt][1]));
                *(uint32_t*)((__half*)Cg + (size_t)(row + 8) * N + col) =
                    h2u(__floats2half2_rn(acc[mt][nt][2], acc[mt][nt][3]));
            }
        }
    }
}

// --------------------------- positions from sorted segment ids ---------------
__global__ void pos_kernel(const int* __restrict__ seg, int* __restrict__ pos) {
    int idx = blockIdx.x * blockDim.x + threadIdx.x;
    if (idx >= MTOT) return;
    int b = idx / Tt;
    int t = idx % Tt;
    const int* row = seg + (size_t)b * Tt;
    int s = row[t];
    int lo = 0, hi = t;
    while (lo < hi) {
        int mid = (lo + hi) >> 1;
        if (row[mid] < s) lo = mid + 1; else hi = mid;
    }
    pos[idx] = t - lo;
}

// ---------------- fused RMSNorm + RoPE, f32 in -> f16 out --------------------
__global__ __launch_bounds__(128)
void rms_rope_kernel(const float* __restrict__ x, const float* __restrict__ scale,
                     const int* __restrict__ pos, __half* __restrict__ outh,
                     int NH, float post_mul) {
    const int bt = blockIdx.x / NH;
    const int h  = blockIdx.x % NH;
    const float* p = x + ((size_t)bt * NH + h) * Kk;
    __half* po = outh + ((size_t)bt * NH + h) * Kk;

    const int i = threadIdx.x;
    float v = p[i];

    __shared__ float red[4];
    __shared__ float sx[Kk];
    float sq = v * v;
#pragma unroll
    for (int o = 16; o; o >>= 1) sq += __shfl_xor_sync(0xffffffffu, sq, o);
    if ((i & 31) == 0) red[i >> 5] = sq;
    __syncthreads();
    float var = (red[0] + red[1] + red[2] + red[3]) * (1.0f / Kk);
    float xn  = v * rsqrtf(var + EPS) * scale[i];
    sx[i] = xn;
    __syncthreads();

    if (i < Kk / 2) {
        float x1 = sx[i];
        float x2 = sx[i + Kk / 2];
        float pp = (float)pos[bt];
        float inv = expf(-logf(ROPE_BASE) * (2.0f * (float)i / (float)Kk));
        float ang = pp * inv;
        float s, c;
        sincosf(ang, &s, &c);
        po[i]           = __float2half_rn((x1 * c - x2 * s) * post_mul);
        po[i + Kk / 2]  = __float2half_rn((x2 * c + x1 * s) * post_mul);
    }
}

// =============================================================================
// Flash attention, fp16 tensor cores (m16n8k16), P kept in registers.
// Block = (32-query tile, g, b); 8 warps; warp w: head w>>1, 16 query rows.
// q is pre-scaled by SOFTMAX_SCALE. Key window [t-pos[t], t].
// =============================================================================
#define KV_STR 136

__device__ __forceinline__ float qmax2(float x) {
    x = fmaxf(x, __shfl_xor_sync(0xffffffffu, x, 1));
    x = fmaxf(x, __shfl_xor_sync(0xffffffffu, x, 2));
    return x;
}
__device__ __forceinline__ float qsum2(float x) {
    x += __shfl_xor_sync(0xffffffffu, x, 1);
    x += __shfl_xor_sync(0xffffffffu, x, 2);
    return x;
}

__global__ __launch_bounds__(256)
void fa16_kernel(const __half* __restrict__ q, const __half* __restrict__ k,
                 const __half* __restrict__ v, const int* __restrict__ pos,
                 __half* __restrict__ out) {
    __shared__ __half Ks[2][32][KV_STR];
    __shared__ __half Vs[2][32][KV_STR];

    const int tid  = threadIdx.x;
    const int lane = tid & 31;
    const int w    = tid >> 5;
    const int t0   = blockIdx.x * 32;
    const int g    = blockIdx.y;
    const int b    = blockIdx.z;

    const int h_local = w >> 1;
    const int q_base  = (w & 1) * 16;
    const int h = g * Rr + h_local;

    const int fr = lane >> 2;
    const int fc = lane & 3;

    const int t_r0 = t0 + q_base + fr;
    const int t_r1 = t_r0 + 8;
    const int w0lo = t_r0 - pos[b * Tt + t_r0];
    const int w1lo = t_r1 - pos[b * Tt + t_r1];

    // Q fragments: 8 chunks of k16
    uint32_t qf[8][4];
    {
        const __half* q0p = q + (((size_t)b * Tt + t_r0) * Hh + h) * Kk;
        const __half* q1p = q + (((size_t)b * Tt + t_r1) * Hh + h) * Kk;
#pragma unroll
        for (int kc = 0; kc < 8; kc++) {
            qf[kc][0] = *(const uint32_t*)(q0p + kc * 16 + 2 * fc);
            qf[kc][1] = *(const uint32_t*)(q1p + kc * 16 + 2 * fc);
            qf[kc][2] = *(const uint32_t*)(q0p + kc * 16 + 8 + 2 * fc);
            qf[kc][3] = *(const uint32_t*)(q1p + kc * 16 + 8 + 2 * fc);
        }
    }

    float oa[16][4];
#pragma unroll
    for (int i = 0; i < 16; i++)
#pragma unroll
        for (int j = 0; j < 4; j++) oa[i][j] = 0.f;
    float m0 = -1e30f, m1 = -1e30f, l0 = 0.f, l1 = 0.f;

    const int s_begin = (t0 - pos[b * Tt + t0]) & ~31;
    const int n_tiles = ((t0 + 31 - s_begin) >> 5) + 1;

    const __half* kg = k + ((size_t)b * Tt * Gg + g) * Kk;
    const __half* vg = v + ((size_t)b * Tt * Gg + g) * Kk;

    auto load_tile = [&](int buf, int s_tile) {
#pragma unroll
        for (int i = 0; i < 2; i++) {
            int idx = tid + i * 256;
            int r = idx >> 4, c = (idx & 15) * 8;
            uint32_t dst = (uint32_t)__cvta_generic_to_shared(&Ks[buf][r][c]);
            const __half* src = kg + (size_t)(s_tile + r) * Gg * Kk + c;
            asm volatile("cp.async.cg.shared.global [%0], [%1], 16;\n"
                         :: "r"(dst), "l"(src));
        }
#pragma unroll
        for (int i = 0; i < 2; i++) {
            int idx = tid + i * 256;
            int r = idx >> 4, c = (idx & 15) * 8;
            uint32_t dst = (uint32_t)__cvta_generic_to_shared(&Vs[buf][r][c]);
            const __half* src = vg + (size_t)(s_tile + r) * Gg * Kk + c;
            asm volatile("cp.async.cg.shared.global [%0], [%1], 16;\n"
                         :: "r"(dst), "l"(src));
        }
        asm volatile("cp.async.commit_group;\n");
    };

    load_tile(0, s_begin);

    for (int it = 0; it < n_tiles; it++) {
        const int s_tile = s_begin + it * 32;
        asm volatile("cp.async.wait_group 0;\n");
        __syncthreads();
        const int cur = it & 1;
        if (it + 1 < n_tiles) load_tile(cur ^ 1, s_tile + 32);

        // ---- scores: S[16,32] = Q @ K^T (q pre-scaled) ----
        float sc[4][4];
#pragma unroll
        for (int nt = 0; nt < 4; nt++)
#pragma unroll
            for (int i = 0; i < 4; i++) sc[nt][i] = 0.f;

#pragma unroll
        for (int nt = 0; nt < 4; nt++) {
#pragma unroll
            for (int kcp = 0; kcp < 4; kcp++) {
                uint32_t r0, r1, r2, r3;
                uint32_t addr = (uint32_t)__cvta_generic_to_shared(
                    &Ks[cur][nt * 8 + (lane & 7)][kcp * 32 + 8 * (lane >> 3)]);
                asm volatile("ldmatrix.sync.aligned.m8n8.x4.shared.b16 "
                             "{%0,%1,%2,%3}, [%4];\n"
                             : "=r"(r0), "=r"(r1), "=r"(r2), "=r"(r3)
                             : "r"(addr));
                MMA_F16(sc[nt], qf[2 * kcp], r0, r1);
                MMA_F16(sc[nt], qf[2 * kcp + 1], r2, r3);
            }
        }

        // ---- mask + online softmax ----
        float x[4][4];
        float rm0 = -1e30f, rm1 = -1e30f;
#pragma unroll
        for (int nt = 0; nt < 4; nt++) {
            int s_b = s_tile + nt * 8 + fc * 2;
            x[nt][0] = (s_b     >= w0lo && s_b     <= t_r0) ? sc[nt][0] : -1e30f;
            x[nt][1] = (s_b + 1 >= w0lo && s_b + 1 <= t_r0) ? sc[nt][1] : -1e30f;
            x[nt][2] = (s_b     >= w1lo && s_b     <= t_r1) ? sc[nt][2] : -1e30f;
            x[nt][3] = (s_b + 1 >= w1lo && s_b + 1 <= t_r1) ? sc[nt][3] : -1e30f;
            rm0 = fmaxf(rm0, fmaxf(x[nt][0], x[nt][1]));
            rm1 = fmaxf(rm1, fmaxf(x[nt][2], x[nt][3]));
        }
        rm0 = qmax2(rm0);
        rm1 = qmax2(rm1);
        const float mn0 = fmaxf(m0, rm0);
        const float mn1 = fmaxf(m1, rm1);
        const float corr0 = __expf(m0 - mn0);
        const float corr1 = __expf(m1 - mn1);

        float e[4][4];
        float rs0 = 0.f, rs1 = 0.f;
#pragma unroll
        for (int nt = 0; nt < 4; nt++) {
            e[nt][0] = (x[nt][0] > -1e29f) ? __expf(x[nt][0] - mn0) : 0.f;
            e[nt][1] = (x[nt][1] > -1e29f) ? __expf(x[nt][1] - mn0) : 0.f;
            e[nt][2] = (x[nt][2] > -1e29f) ? __expf(x[nt][2] - mn1) : 0.f;
            e[nt][3] = (x[nt][3] > -1e29f) ? __expf(x[nt][3] - mn1) : 0.f;
            rs0 += e[nt][0] + e[nt][1];
            rs1 += e[nt][2] + e[nt][3];
        }
        l0 = l0 * corr0 + qsum2(rs0);
        l1 = l1 * corr1 + qsum2(rs1);
        m0 = mn0;
        m1 = mn1;

        // ---- pack P into A fragments (registers only) ----
        uint32_t pa[2][4];
#pragma unroll
        for (int kc2 = 0; kc2 < 2; kc2++) {
            pa[kc2][0] = h2u(__floats2half2_rn(e[2 * kc2][0],     e[2 * kc2][1]));
            pa[kc2][1] = h2u(__floats2half2_rn(e[2 * kc2][2],     e[2 * kc2][3]));
            pa[kc2][2] = h2u(__floats2half2_rn(e[2 * kc2 + 1][0], e[2 * kc2 + 1][1]));
            pa[kc2][3] = h2u(__floats2half2_rn(e[2 * kc2 + 1][2], e[2 * kc2 + 1][3]));
        }

#pragma unroll
        for (int nt = 0; nt < 16; nt++) {
            oa[nt][0] *= corr0;
            oa[nt][1] *= corr0;
            oa[nt][2] *= corr1;
            oa[nt][3] *= corr1;
        }

        // ---- O += P @ V ----
#pragma unroll
        for (int nt2 = 0; nt2 < 8; nt2++) {
#pragma unroll
            for (int kc2 = 0; kc2 < 2; kc2++) {
                uint32_t r0, r1, r2, r3;
                uint32_t addr = (uint32_t)__cvta_generic_to_shared(
                    &Vs[cur][kc2 * 16 + 8 * ((lane >> 3) & 1) + (lane & 7)]
                       [nt2 * 16 + 8 * (lane >> 4)]);
                asm volatile("ldmatrix.sync.aligned.m8n8.x4.trans.shared.b16 "
                             "{%0,%1,%2,%3}, [%4];\n"
                             : "=r"(r0), "=r"(r1), "=r"(r2), "=r"(r3)
                             : "r"(addr));
                MMA_F16(oa[2 * nt2], pa[kc2], r0, r1);
                MMA_F16(oa[2 * nt2 + 1], pa[kc2], r2, r3);
            }
        }
        __syncthreads();
    }

    // ---- epilogue: write half ----
    const float inv0 = 1.0f / l0;
    const float inv1 = 1.0f / l1;
    __half* o0 = out + (((size_t)b * Tt + t_r0) * Hh + h) * Kk;
    __half* o1 = out + (((size_t)b * Tt + t_r1) * Hh + h) * Kk;
#pragma unroll
    for (int nt = 0; nt < 16; nt++) {
        int d = nt * 8 + fc * 2;
        *(uint32_t*)(o0 + d) = h2u(__floats2half2_rn(oa[nt][0] * inv0, oa[nt][1] * inv0));
        *(uint32_t*)(o1 + d) = h2u(__floats2half2_rn(oa[nt][2] * inv1, oa[nt][3] * inv1));
    }
}

// --------------------------- launch --------------------------------------
extern "C" void kernel_launch(void* const* d_in, const int* in_sizes, int n_in,
                              void* d_out, int out_size) {
    const float* hidden  = (const float*)d_in[0];
    const float* wq      = (const float*)d_in[1];
    const float* wk      = (const float*)d_in[2];
    const float* wv      = (const float*)d_in[3];
    const float* wo      = (const float*)d_in[4];
    const float* q_scale = (const float*)d_in[5];
    const float* k_scale = (const float*)d_in[6];
    const int*   seg     = (const int*)d_in[7];
    float* out = (float*)d_out;

    float *qb, *kb;
    int* posb;
    __half *h16, *wq16, *wk16, *wv16, *wo16, *q16, *k16, *v16, *a16;
    cudaGetSymbolAddress((void**)&qb, g_q);
    cudaGetSymbolAddress((void**)&kb, g_k);
    cudaGetSymbolAddress((void**)&posb, g_pos);
    cudaGetSymbolAddress((void**)&h16, g_h16);
    cudaGetSymbolAddress((void**)&wq16, g_wq16);
    cudaGetSymbolAddress((void**)&wk16, g_wk16);
    cudaGetSymbolAddress((void**)&wv16, g_wv16);
    cudaGetSymbolAddress((void**)&wo16, g_wo16);
    cudaGetSymbolAddress((void**)&q16, g_q16);
    cudaGetSymbolAddress((void**)&k16, g_k16);
    cudaGetSymbolAddress((void**)&v16, g_v16);
    cudaGetSymbolAddress((void**)&a16, g_a16);

    // 0) convert inputs to fp16
    {
        int nh = MTOT * Dd;
        f2h_kernel<<<nh / (256 * 8), 256>>>(hidden, h16, nh);
        int nq = Dd * Hh * Kk;
        f2h_kernel<<<nq / (256 * 8), 256>>>(wq, wq16, nq);
        int nk = Dd * Gg * Kk;
        f2h_kernel<<<nk / (256 * 8), 256>>>(wk, wk16, nk);
        f2h_kernel<<<nk / (256 * 8), 256>>>(wv, wv16, nk);
        int no = Hh * Kk * Dd;
        f2h_kernel<<<no / (256 * 8), 256>>>(wo, wo16, no);
    }

    // 1) QKV projections
    {
        dim3 blk(256);
        dim3 grdQ((Hh * Kk) / 128, MTOT / 128);
        hgemm_kernel<float><<<grdQ, blk>>>(MTOT, Hh * Kk, Dd, h16, wq16, qb);
        dim3 grdK((Gg * Kk) / 128, MTOT / 128);
        hgemm_kernel<float><<<grdK, blk>>>(MTOT, Gg * Kk, Dd, h16, wk16, kb);
        hgemm_kernel<__half><<<grdK, blk>>>(MTOT, Gg * Kk, Dd, h16, wv16, v16);
    }

    // 2) positions
    pos_kernel<<<(MTOT + 255) / 256, 256>>>(seg, posb);

    // 3) RMSNorm + RoPE -> fp16 (q pre-scaled by softmax scale)
    rms_rope_kernel<<<MTOT * Hh, 128>>>(qb, q_scale, posb, q16, Hh, SOFTMAX_SCALE);
    rms_rope_kernel<<<MTOT * Gg, 128>>>(kb, k_scale, posb, k16, Gg, 1.0f);

    // 4) flash attention (fp16)
    {
        dim3 grd(Tt / 32, Gg, Bb);
        fa16_kernel<<<grd, 256>>>(q16, k16, v16, posb, a16);
    }

    // 5) output projection (f32 out)
    {
        dim3 blk(256);
        dim3 grd(Dd / 128, MTOT / 128);
        hgemm_kernel<float><<<grd, blk>>>(MTOT, Dd, Hh * Kk, a16, wo16, out);
    }
}